// round 15
// baseline (speedup 1.0000x reference)
#include <cuda_runtime.h>
#include <cuda_fp16.h>
#include <math.h>
#include <stdint.h>

// ---------------------------------------------------------------------------
// Problem constants
// ---------------------------------------------------------------------------
#define Bn   4
#define Cc   192
#define C2   384
#define Hh   96
#define Ww   96
#define HW   (Hh*Ww)          // 9216
#define NH   8
#define HD   24
#define Gg   8
#define CG   24

// scratch offsets (in floats / uint32 slots)
#define OFF_QKV1   0ul
#define OFF_QKV    14155776ul
#define OFF_CAT    28311552ul
#define OFF_K2     42467328ul     // 3250176
#define OFF_OFF    45717504ul     // 663552
#define OFF_K      46381056ul     // 7077888
#define OFF_QN     53458944ul
#define OFF_KN     53459712ul
#define OFF_ATTN   53460480ul
#define OFF_WK3H   53478912ul     // 663552
#define OFF_WK2H   54142464ul     // 663552
#define OFF_WK4H   54806016ul     // 31104
#define OFF_WQKVH  54837120ul     // 36864
#define OFF_WPWH   54873984ul     // 18432
#define OFF_WPROJH 54892416ul     // 18432
#define OFF_XH     54910848ul     // 3538944
#define OFF_CATH   58449792ul     // 7077888
#define OFF_POOLH  65527680ul     // 1769472
#define OFF_SCH    67297152ul     // 7077888
#define OFF_FEATH  74375040ul     // 3538944
#define OFF_AOH    77913984ul     // 3538944
#define SCRATCH_TOTAL 81452928ul

__device__ float g_scratch[SCRATCH_TOTAL];

// ---------------------------------------------------------------------------
// helpers
// ---------------------------------------------------------------------------
__device__ __forceinline__ uint32_t pack_h2(float lo, float hi) {
    __half2 h = __floats2half2_rn(lo, hi);
    return *reinterpret_cast<uint32_t*>(&h);
}

__device__ __forceinline__ void mma_16x8x16(float* c, const uint32_t* a,
                                            uint32_t b0, uint32_t b1) {
    asm volatile(
        "mma.sync.aligned.m16n8k16.row.col.f32.f16.f16.f32 "
        "{%0,%1,%2,%3}, {%4,%5,%6,%7}, {%8,%9}, {%0,%1,%2,%3};\n"
        : "+f"(c[0]), "+f"(c[1]), "+f"(c[2]), "+f"(c[3])
        : "r"(a[0]), "r"(a[1]), "r"(a[2]), "r"(a[3]), "r"(b0), "r"(b1));
}

__device__ __forceinline__ void cpasync4(uint32_t saddr, const void* g, bool pred) {
    int sz = pred ? 4 : 0;
    asm volatile("cp.async.ca.shared.global [%0], [%1], 4, %2;\n"
                 :: "r"(saddr), "l"(g), "r"(sz));
}
__device__ __forceinline__ void cpasync16(uint32_t saddr, const void* g) {
    asm volatile("cp.async.cg.shared.global [%0], [%1], 16;\n"
                 :: "r"(saddr), "l"(g));
}
__device__ __forceinline__ void cpasync16ca(uint32_t saddr, const void* g, bool pred) {
    int sz = pred ? 16 : 0;
    asm volatile("cp.async.ca.shared.global [%0], [%1], 16, %2;\n"
                 :: "r"(saddr), "l"(g), "r"(sz));
}
#define CP_COMMIT() asm volatile("cp.async.commit_group;\n" ::: "memory")
#define CP_WAIT0()  asm volatile("cp.async.wait_group 0;\n" ::: "memory")

// ---------------------------------------------------------------------------
// 3x3 weights: permute to tap-major K AND pack half2 K-pairs.
// ---------------------------------------------------------------------------
__global__ void permpack3_kernel(const float* __restrict__ W,
                                 uint32_t* __restrict__ Wph, int M, int Cin)
{
    int K2 = Cin * 9 / 2;
    int i = blockIdx.x * 256 + threadIdx.x;
    if (i >= M * K2) return;
    int m = i / K2;
    int r = i - m * K2;
    int t  = r / (Cin / 2);
    int ic = 2 * (r - t * (Cin / 2));
    float lo = W[(size_t)m * Cin * 9 + ic * 9 + t];
    float hi = W[(size_t)m * Cin * 9 + (ic + 1) * 9 + t];
    Wph[i] = pack_h2(lo, hi);
}

// 1x1 weights: pack half2 K-pairs
__global__ void packw1_kernel(const float* __restrict__ W,
                              uint32_t* __restrict__ Wph, int M, int K)
{
    int K2 = K / 2;
    int i = blockIdx.x * 256 + threadIdx.x;
    if (i >= M * K2) return;
    int m = i / K2;
    int kp = i - m * K2;
    Wph[i] = pack_h2(W[(size_t)m * K + 2 * kp], W[(size_t)m * K + 2 * kp + 1]);
}

// fp32 [2P][4*N4] -> half2 channel-pair packed (external input x only)
__global__ void halfpack4_kernel(const float* __restrict__ X,
                                 uint4* __restrict__ Xp, int P, int N4)
{
    int i = blockIdx.x * 256 + threadIdx.x;
    if (i >= P * N4) return;
    int pr = i / N4, n4 = i - pr * N4;
    float4 a = reinterpret_cast<const float4*>(X)[(size_t)(2 * pr) * N4 + n4];
    float4 b = reinterpret_cast<const float4*>(X)[(size_t)(2 * pr + 1) * N4 + n4];
    uint4 o;
    o.x = pack_h2(a.x, b.x);
    o.y = pack_h2(a.y, b.y);
    o.z = pack_h2(a.z, b.z);
    o.w = pack_h2(a.w, b.w);
    Xp[i] = o;
}

// ---------------------------------------------------------------------------
// fp16 tensor-core implicit-GEMM conv, BK=32 (two k-steps per sync).
// SIG=0: fp32 output (+optional bias). SIG=1 (k3): epilogue computes
//   half( acc * sigmoid(CAT + upsample(K2)) ) and stores u16 halves directly
//   into the channel-pair packed SCH buffer (race-free byte-granular stores).
// ---------------------------------------------------------------------------
template<int KS, int FM, int SIG>
__global__ __launch_bounds__(256)
void conv_mma(const uint32_t* __restrict__ Wph,
              const uint32_t* __restrict__ Xp,
              void* __restrict__ Yout,
              const float* __restrict__ bias,
              const float* __restrict__ CATf,
              const float* __restrict__ K2f,
              int M, int Cin, int IH, int IW,
              int OH, int OW, int pad)
{
    constexpr int BM    = 32 * FM;
    constexpr int BK    = 32;
    constexpr int ASTR  = 20;
    constexpr int B2STR = 136;
    constexpr int ACP   = BM * 4;
    constexpr int AIT   = (ACP + 255) / 256;

    __shared__ uint32_t As2[2][BM * ASTR];
    __shared__ uint32_t Bs2[2][16 * B2STR];

    const int N   = OH * OW;
    const int K   = Cin * KS * KS;
    const int K2  = K >> 1;
    const int IHW = IH * IW;
    const int bz  = blockIdx.z;
    const int m0  = blockIdx.y * BM;
    const int n0  = blockIdx.x * 128;

    const int tid  = threadIdx.x;
    const int wid  = tid >> 5;
    const int lane = tid & 31;
    const int wm   = wid & 1;
    const int wn   = wid >> 1;
    const int mbase = wm * (16 * FM);
    const int nbase = wn * 32;
    const int lg = lane >> 2;
    const int lt = lane & 3;

    const uint32_t* Xb = Xp + (size_t)bz * (Cin >> 1) * IHW;

    float acc[FM][4][4];
    #pragma unroll
    for (int f = 0; f < FM; ++f)
        #pragma unroll
        for (int nf = 0; nf < 4; ++nf)
            #pragma unroll
            for (int r = 0; r < 4; ++r) acc[f][nf][r] = 0.f;

    const int bn = tid & 127;
    const int gn = n0 + bn;
    const bool nvalid = gn < N;
    int oy = 0, ox = 0;
    if (KS == 3) { int g = nvalid ? gn : 0; oy = g / OW; ox = g - oy * OW; }

    auto issueA = [&](int k0, int buf) {
        #pragma unroll
        for (int r = 0; r < AIT; ++r) {
            int idx = tid + 256 * r;
            if (ACP >= 256 * (r + 1) || idx < ACP) {
                int m = idx >> 2;
                int q = idx & 3;
                int gm = m0 + m;
                uint32_t s = (uint32_t)__cvta_generic_to_shared(
                    &As2[buf][m * ASTR + q * 4]);
                cpasync16ca(s, Wph + (size_t)gm * K2 + (k0 >> 1) + q * 4, gm < M);
            }
        }
    };
    auto issueB = [&](int k0, int buf) {
        if (KS == 1) {
            #pragma unroll
            for (int r = 0; r < 2; ++r) {
                int idx = tid + 256 * r;
                int row = idx >> 5;
                int c4  = (idx & 31) * 4;
                uint32_t s = (uint32_t)__cvta_generic_to_shared(&Bs2[buf][row * B2STR + c4]);
                cpasync16(s, Xb + (size_t)((k0 >> 1) + row) * N + n0 + c4);
            }
        } else {
            int tp  = k0 / Cin;
            int icb = k0 - tp * Cin;
            int tdy = (tp >= 6) ? 2 : ((tp >= 3) ? 1 : 0);
            int tdx = tp - 3 * tdy;
            int iy  = oy + tdy - pad;
            int ix  = ox + tdx - pad;
            bool ok = nvalid && iy >= 0 && iy < IH && ix >= 0 && ix < IW;
            const uint32_t* base = Xb + (size_t)(icb >> 1) * IHW + iy * IW + ix;
            #pragma unroll
            for (int r = 0; r < 8; ++r) {
                int kp = (tid >> 7) + 2 * r;
                uint32_t s = (uint32_t)__cvta_generic_to_shared(&Bs2[buf][kp * B2STR + bn]);
                cpasync4(s, base + (size_t)kp * IHW, ok);
            }
        }
    };
    auto compute = [&](int buf) {
        #pragma unroll
        for (int ks = 0; ks < 2; ++ks) {
            const int kb = ks * 8;
            uint32_t a[FM][4];
            #pragma unroll
            for (int f = 0; f < FM; ++f) {
                int mr = mbase + f * 16 + lg;
                a[f][0] = As2[buf][mr * ASTR + kb + lt];
                a[f][1] = As2[buf][(mr + 8) * ASTR + kb + lt];
                a[f][2] = As2[buf][mr * ASTR + kb + lt + 4];
                a[f][3] = As2[buf][(mr + 8) * ASTR + kb + lt + 4];
            }
            #pragma unroll
            for (int nf = 0; nf < 4; ++nf) {
                int nc = nbase + nf * 8 + lg;
                uint32_t b0 = Bs2[buf][(kb + lt) * B2STR + nc];
                uint32_t b1 = Bs2[buf][(kb + lt + 4) * B2STR + nc];
                #pragma unroll
                for (int f = 0; f < FM; ++f)
                    mma_16x8x16(acc[f][nf], a[f], b0, b1);
            }
        }
    };

    const int kTiles = K / BK;
    issueA(0, 0); issueB(0, 0); CP_COMMIT();
    CP_WAIT0(); __syncthreads();

    for (int t = 0; t < kTiles; ++t) {
        if (t + 1 < kTiles) {
            issueA((t + 1) * BK, (t + 1) & 1);
            issueB((t + 1) * BK, (t + 1) & 1);
            CP_COMMIT();
        }
        compute(t & 1);
        if (t + 1 < kTiles) {
            CP_WAIT0(); __syncthreads();
        }
    }

    // ---- epilogue ----
    #pragma unroll
    for (int f = 0; f < FM; ++f) {
        int r0 = m0 + mbase + f * 16 + lg;
        #pragma unroll
        for (int nf = 0; nf < 4; ++nf) {
            int cb = n0 + nbase + nf * 8 + 2 * lt;
            #pragma unroll
            for (int rr = 0; rr < 2; ++rr) {
                int m = r0 + rr * 8;
                if (m >= M) continue;
                float bval = (!SIG && bias) ? bias[m] : 0.f;
                #pragma unroll
                for (int cc = 0; cc < 2; ++cc) {
                    int n = cb + cc;
                    if (n >= N) continue;
                    float v = acc[f][nf][rr * 2 + cc] + bval;
                    if (SIG) {
                        int yy = n / OW, xx = n - yy * OW;
                        int iy = (yy * 46) / 96, ix = (xx * 46) / 96;
                        size_t bc = (size_t)bz * M + m;
                        float sg = CATf[bc * N + n] + K2f[bc * 2116 + iy * 46 + ix];
                        float r = v / (1.f + expf(-sg));
                        reinterpret_cast<__half*>(Yout)[
                            (((size_t)bz * (M >> 1) + (m >> 1)) * N + n) * 2 + (m & 1)]
                            = __float2half_rn(r);
                    } else {
                        ((float*)Yout)[((size_t)bz * M + m) * N + n] = v;
                    }
                }
            }
        }
    }
}

// ---------------------------------------------------------------------------
// grouped 3x3 conv, smem-tiled
// ---------------------------------------------------------------------------
__global__ __launch_bounds__(256)
void dwconv2_kernel(const float* __restrict__ X,
                    const float* __restrict__ W,
                    float* __restrict__ Y)
{
    __shared__ float xs[2][34][35];
    __shared__ float ws[36];

    const int tile = blockIdx.x;
    const int g    = blockIdx.y;
    const int b    = blockIdx.z;
    const int ty0  = (tile / 3) * 32;
    const int tx0  = (tile % 3) * 32;
    const int tid  = threadIdx.x;

    if (tid < 36) ws[tid] = W[(size_t)g * 36 + tid];

    for (int e = tid; e < 2 * 34 * 34; e += 256) {
        int c  = e / (34 * 34);
        int r  = e - c * 34 * 34;
        int yy = r / 34, xx = r - yy * 34;
        int gy = ty0 + yy - 1, gx = tx0 + xx - 1;
        float v = 0.f;
        if (gy >= 0 && gy < Hh && gx >= 0 && gx < Ww)
            v = X[((size_t)b * C2 + 2 * g + c) * HW + gy * Ww + gx];
        xs[c][yy][xx] = v;
    }
    __syncthreads();

    const int x  = tid & 31;
    const int yb = (tid >> 5) * 4;
    #pragma unroll
    for (int j = 0; j < 4; ++j) {
        int y = yb + j;
        float a0 = 0.f, a1 = 0.f;
        #pragma unroll
        for (int c = 0; c < 2; ++c)
            #pragma unroll
            for (int ky = 0; ky < 3; ++ky)
                #pragma unroll
                for (int kx = 0; kx < 3; ++kx) {
                    float v = xs[c][y + ky][x + kx];
                    a0 += v * ws[c * 9 + ky * 3 + kx];
                    a1 += v * ws[18 + c * 9 + ky * 3 + kx];
                }
        size_t o = ((size_t)b * C2 + 2 * g) * HW + (ty0 + y) * Ww + tx0 + x;
        Y[o]      = a0;
        Y[o + HW] = a1;
    }
}

// cat: channel-pair thread; writes CAT fp32 + CATH packed in one pass.
__global__ void catpack_kernel(const float* __restrict__ QKV,
                               const float* __restrict__ Yin,
                               float* __restrict__ CAT,
                               uint4* __restrict__ CATH)
{
    const int NP = C2 / 2;
    const int N4 = HW / 4;
    int i = blockIdx.x * 256 + threadIdx.x;
    if (i >= Bn * NP * N4) return;
    int p4 = i % N4;
    int pr = (i / N4) % NP;
    int b  = i / (N4 * NP);
    int c0 = 2 * pr;
    float4 a, bv;
    if (c0 < Cc) {
        a  = reinterpret_cast<const float4*>(QKV + ((size_t)b * C2 + c0) * HW)[p4];
        bv = reinterpret_cast<const float4*>(QKV + ((size_t)b * C2 + c0 + 1) * HW)[p4];
    } else {
        a  = reinterpret_cast<const float4*>(Yin + ((size_t)b * Cc + (c0 - Cc)) * HW)[p4];
        bv = reinterpret_cast<const float4*>(Yin + ((size_t)b * Cc + (c0 - Cc) + 1) * HW)[p4];
    }
    reinterpret_cast<float4*>(CAT + ((size_t)b * C2 + c0) * HW)[p4]     = a;
    reinterpret_cast<float4*>(CAT + ((size_t)b * C2 + c0 + 1) * HW)[p4] = bv;
    uint4 o;
    o.x = pack_h2(a.x, bv.x);
    o.y = pack_h2(a.y, bv.y);
    o.z = pack_h2(a.z, bv.z);
    o.w = pack_h2(a.w, bv.w);
    CATH[((size_t)b * NP + pr) * N4 + p4] = o;
}

// 2x2 avg pool, packed-only output
__global__ void poolpack_kernel(const float* __restrict__ X, uint4* __restrict__ Yp)
{
    const int NP   = C2 / 2;
    const int OHW4 = 48 * 48 / 4;
    int i = blockIdx.x * 256 + threadIdx.x;
    if (i >= Bn * NP * OHW4) return;
    int r  = i % OHW4;
    int pr = (i / OHW4) % NP;
    int b  = i / (OHW4 * NP);
    int y  = r / 12;
    int x8 = (r % 12) * 8;
    float pv[2][4];
    #pragma unroll
    for (int c = 0; c < 2; ++c) {
        const float* xp = X + ((size_t)b * C2 + 2 * pr + c) * HW;
        float4 r0a = *reinterpret_cast<const float4*>(xp + (2 * y) * Ww + x8);
        float4 r0b = *reinterpret_cast<const float4*>(xp + (2 * y) * Ww + x8 + 4);
        float4 r1a = *reinterpret_cast<const float4*>(xp + (2 * y + 1) * Ww + x8);
        float4 r1b = *reinterpret_cast<const float4*>(xp + (2 * y + 1) * Ww + x8 + 4);
        pv[c][0] = (r0a.x + r0a.y + r1a.x + r1a.y) * 0.25f;
        pv[c][1] = (r0a.z + r0a.w + r1a.z + r1a.w) * 0.25f;
        pv[c][2] = (r0b.x + r0b.y + r1b.x + r1b.y) * 0.25f;
        pv[c][3] = (r0b.z + r0b.w + r1b.z + r1b.w) * 0.25f;
    }
    uint4 o;
    o.x = pack_h2(pv[0][0], pv[1][0]);
    o.y = pack_h2(pv[0][1], pv[1][1]);
    o.z = pack_h2(pv[0][2], pv[1][2]);
    o.w = pack_h2(pv[0][3], pv[1][3]);
    Yp[((size_t)b * NP + pr) * OHW4 + r] = o;
}

// ---------------------------------------------------------------------------
// fused deformable conv; float4 weight LDS; writes packed half2 relu output.
// ---------------------------------------------------------------------------
__global__ __launch_bounds__(128)
void deform_kernel(const float* __restrict__ Q,
                   const float* __restrict__ OFF,
                   const float* __restrict__ W,
                   const float* __restrict__ Bias,
                   uint32_t* __restrict__ Yp)
{
    __shared__ __align__(16) float ws2[216 * 24];   // [(i*9+t)][24], rows 96B-aligned
    const int g = blockIdx.y;
    const int b = blockIdx.z;
    const int tid = threadIdx.x;

    for (int e = tid; e < 216 * 24; e += 128) {
        int it = e / 24;
        int o  = e - it * 24;
        ws2[e] = W[(size_t)(g * CG + o) * 216 + it];
    }
    __syncthreads();

    int p = blockIdx.x * 128 + tid;
    int y = p / Ww, x = p % Ww;
    const float* offb = OFF + (size_t)b * 18 * HW;

    float acc[24];
    #pragma unroll
    for (int o = 0; o < 24; ++o) acc[o] = Bias[g * CG + o];

    const float* qc = Q + ((size_t)b * C2 + g * CG) * HW;

    for (int t = 0; t < 9; ++t) {
        float dy = offb[(size_t)(2 * t) * HW + p];
        float dx = offb[(size_t)(2 * t + 1) * HW + p];
        float m  = 1.f / (1.f + expf(-offb[(size_t)t * HW + p]));
        float py = dy + (float)(y - 1 + t / 3);
        float px = dx + (float)(x - 1 + t % 3);
        float y0f = floorf(py), x0f = floorf(px);
        int   y0 = (int)y0f,    x0 = (int)x0f;
        float fy = py - y0f,    fx = px - x0f;
        float w00 = (1.f - fy) * (1.f - fx);
        float w01 = (1.f - fy) * fx;
        float w10 = fy * (1.f - fx);
        float w11 = fy * fx;
        bool vy0 = (y0 >= 0 && y0 <= Hh - 1), vy1 = (y0 + 1 >= 0 && y0 + 1 <= Hh - 1);
        bool vx0 = (x0 >= 0 && x0 <= Ww - 1), vx1 = (x0 + 1 >= 0 && x0 + 1 <= Ww - 1);
        int cy0 = min(max(y0, 0), Hh - 1),     cy1 = min(max(y0 + 1, 0), Hh - 1);
        int cx0 = min(max(x0, 0), Ww - 1),     cx1 = min(max(x0 + 1, 0), Ww - 1);
        int i00 = cy0 * Ww + cx0, i01 = cy0 * Ww + cx1;
        int i10 = cy1 * Ww + cx0, i11 = cy1 * Ww + cx1;
        w00 = (vy0 && vx0) ? w00 * m : 0.f;
        w01 = (vy0 && vx1) ? w01 * m : 0.f;
        w10 = (vy1 && vx0) ? w10 * m : 0.f;
        w11 = (vy1 && vx1) ? w11 * m : 0.f;

        #pragma unroll
        for (int i = 0; i < 24; ++i) {
            const float* qp = qc + (size_t)i * HW;
            float val = w00 * qp[i00] + w01 * qp[i01] + w10 * qp[i10] + w11 * qp[i11];
            const float4* wr4 = reinterpret_cast<const float4*>(&ws2[(i * 9 + t) * 24]);
            #pragma unroll
            for (int o4 = 0; o4 < 6; ++o4) {
                float4 w4 = wr4[o4];
                acc[4 * o4 + 0] += val * w4.x;
                acc[4 * o4 + 1] += val * w4.y;
                acc[4 * o4 + 2] += val * w4.z;
                acc[4 * o4 + 3] += val * w4.w;
            }
        }
    }
    #pragma unroll
    for (int u = 0; u < 12; ++u) {
        uint32_t v = pack_h2(fmaxf(acc[2 * u], 0.f), fmaxf(acc[2 * u + 1], 0.f));
        Yp[((size_t)b * (Cc / 2) + g * 12 + u) * HW + p] = v;
    }
}

// ---------------------------------------------------------------------------
// row L2 norms (float4)
// ---------------------------------------------------------------------------
__global__ void rownorm_kernel(const float* __restrict__ QKV,
                               const float* __restrict__ Kb,
                               float* __restrict__ QN,
                               float* __restrict__ KN)
{
    int row   = blockIdx.x;
    int which = row / (Bn * Cc);
    row %= (Bn * Cc);
    int b = row / Cc, c = row % Cc;
    const float* src = which ? (Kb + ((size_t)b * Cc + c) * HW)
                             : (QKV + ((size_t)b * C2 + c) * HW);
    float s = 0.f;
    for (int n = threadIdx.x; n < HW / 4; n += 256) {
        float4 v = reinterpret_cast<const float4*>(src)[n];
        s += v.x * v.x + v.y * v.y + v.z * v.z + v.w * v.w;
    }
    __shared__ float sm[256];
    sm[threadIdx.x] = s;
    __syncthreads();
    for (int d = 128; d > 0; d >>= 1) {
        if (threadIdx.x < d) sm[threadIdx.x] += sm[threadIdx.x + d];
        __syncthreads();
    }
    if (threadIdx.x == 0) {
        float nrm = fmaxf(sqrtf(sm[0]), 1e-12f);
        (which ? KN : QN)[b * Cc + c] = nrm;
    }
}

// ---------------------------------------------------------------------------
// attention: one block per (b,h).  K-head staged through smem.
// ---------------------------------------------------------------------------
#define CNK 384
__global__ __launch_bounds__(256)
void attn2_kernel(const float* __restrict__ QKV,
                  const float* __restrict__ Kb,
                  const float* __restrict__ QN,
                  const float* __restrict__ KN,
                  const float* __restrict__ TEMP,
                  float* __restrict__ ATTN)
{
    __shared__ float ks_[24][CNK + 8];
    __shared__ float logits[24][24];

    const int b = blockIdx.x >> 3;
    const int h = blockIdx.x & 7;
    const int tid  = threadIdx.x;
    const int wid  = tid >> 5;
    const int lane = tid & 31;

    const float* qh = QKV + ((size_t)b * C2 + h * HD) * HW;
    const float* kh = Kb  + ((size_t)b * Cc + h * HD) * HW;

    float acc[3][24];
    #pragma unroll
    for (int r = 0; r < 3; ++r)
        #pragma unroll
        for (int j = 0; j < 24; ++j) acc[r][j] = 0.f;

    const float* q0p = qh + (size_t)(3 * wid + 0) * HW;
    const float* q1p = qh + (size_t)(3 * wid + 1) * HW;
    const float* q2p = qh + (size_t)(3 * wid + 2) * HW;

    for (int n0 = 0; n0 < HW; n0 += CNK) {
        __syncthreads();
        for (int e = tid; e < 24 * (CNK / 4); e += 256) {
            int j = e / (CNK / 4);
            int c = e - j * (CNK / 4);
            float4 v = *reinterpret_cast<const float4*>(kh + (size_t)j * HW + n0 + c * 4);
            ks_[j][c * 4 + 0] = v.x;
            ks_[j][c * 4 + 1] = v.y;
            ks_[j][c * 4 + 2] = v.z;
            ks_[j][c * 4 + 3] = v.w;
        }
        __syncthreads();

        for (int i = lane; i < CNK; i += 32) {
            int n = n0 + i;
            float q0 = q0p[n], q1 = q1p[n], q2 = q2p[n];
            #pragma unroll
            for (int j = 0; j < 24; ++j) {
                float kv = ks_[j][i];
                acc[0][j] += q0 * kv;
                acc[1][j] += q1 * kv;
                acc[2][j] += q2 * kv;
            }
        }
    }

    #pragma unroll
    for (int r = 0; r < 3; ++r)
        #pragma unroll
        for (int j = 0; j < 24; ++j) {
            float v = acc[r][j];
            for (int o = 16; o > 0; o >>= 1) v += __shfl_down_sync(0xffffffffu, v, o);
            if (lane == 0) logits[wid * 3 + r][j] = v;
        }
    __syncthreads();

    if (tid < 24) {
        int i = tid;
        float qn = QN[b * Cc + h * HD + i];
        float tp = TEMP[h];
        float s[24];
        float mx = -1e30f;
        #pragma unroll
        for (int j = 0; j < 24; ++j) {
            s[j] = logits[i][j] / (qn * KN[b * Cc + h * HD + j]) * tp;
            mx = fmaxf(mx, s[j]);
        }
        float sum = 0.f;
        #pragma unroll
        for (int j = 0; j < 24; ++j) { s[j] = expf(s[j] - mx); sum += s[j]; }
        float inv = 1.f / sum;
        #pragma unroll
        for (int j = 0; j < 24; ++j)
            ATTN[(((size_t)b * NH + h) * HD + i) * HD + j] = s[j] * inv;
    }
}

// out = attn @ v ; writes packed half2 directly
__global__ void attnv_kernel(const float* __restrict__ ATTN,
                             const float* __restrict__ QKV,
                             uint32_t* __restrict__ AOp)
{
    int h = blockIdx.y, b = blockIdx.z;
    int n = blockIdx.x * 256 + threadIdx.x;
    __shared__ float a_s[HD * HD];
    for (int e = threadIdx.x; e < HD * HD; e += 256)
        a_s[e] = ATTN[((size_t)b * NH + h) * HD * HD + e];
    __syncthreads();
    const float* vb = QKV + ((size_t)b * C2 + Cc + h * HD) * HW;
    float acc[HD] = {};
    #pragma unroll
    for (int j = 0; j < HD; ++j) {
        float vv = vb[(size_t)j * HW + n];
        #pragma unroll
        for (int i = 0; i < HD; ++i) acc[i] += a_s[i * HD + j] * vv;
    }
    #pragma unroll
    for (int u = 0; u < HD / 2; ++u)
        AOp[((size_t)b * (Cc / 2) + h * (HD / 2) + u) * HW + n] =
            pack_h2(acc[2 * u], acc[2 * u + 1]);
}

// ---------------------------------------------------------------------------
// launcher
// ---------------------------------------------------------------------------
extern "C" void kernel_launch(void* const* d_in, const int* in_sizes, int n_in,
                              void* d_out, int out_size)
{
    const float* x           = (const float*)d_in[0];
    const float* y           = (const float*)d_in[1];
    const float* temperature = (const float*)d_in[2];
    const float* qkv_w       = (const float*)d_in[3];
    const float* qkv_conv_w  = (const float*)d_in[4];
    const float* proj_w      = (const float*)d_in[5];
    const float* k2_w        = (const float*)d_in[6];
    const float* k3_w        = (const float*)d_in[7];
    const float* k4_w        = (const float*)d_in[8];
    const float* deform_w    = (const float*)d_in[9];
    const float* deform_b    = (const float*)d_in[10];
    const float* pw_w        = (const float*)d_in[11];
    const float* pw_b        = (const float*)d_in[12];
    float* out = (float*)d_out;

    float* S = nullptr;
    cudaGetSymbolAddress((void**)&S, g_scratch);
    float* QKV1 = S + OFF_QKV1;
    float* QKV  = S + OFF_QKV;
    float* CAT  = S + OFF_CAT;
    float* K2   = S + OFF_K2;
    float* OFFb = S + OFF_OFF;
    float* Kb   = S + OFF_K;
    float* QN   = S + OFF_QN;
    float* KN   = S + OFF_KN;
    float* ATTN = S + OFF_ATTN;
    uint32_t* WK3H   = (uint32_t*)(S + OFF_WK3H);
    uint32_t* WK2H   = (uint32_t*)(S + OFF_WK2H);
    uint32_t* WK4H   = (uint32_t*)(S + OFF_WK4H);
    uint32_t* WQKVH  = (uint32_t*)(S + OFF_WQKVH);
    uint32_t* WPWH   = (uint32_t*)(S + OFF_WPWH);
    uint32_t* WPROJH = (uint32_t*)(S + OFF_WPROJH);
    uint32_t* XH    = (uint32_t*)(S + OFF_XH);
    uint32_t* CATH  = (uint32_t*)(S + OFF_CATH);
    uint32_t* POOLH = (uint32_t*)(S + OFF_POOLH);
    uint32_t* SCH   = (uint32_t*)(S + OFF_SCH);
    uint32_t* FEATH = (uint32_t*)(S + OFF_FEATH);
    uint32_t* AOH   = (uint32_t*)(S + OFF_AOH);

    // 0) weight permute+pack, 1x1 weight pack, pack x
    permpack3_kernel<<<(663552 + 255) / 256, 256>>>(k3_w, WK3H, C2, C2);
    permpack3_kernel<<<(663552 + 255) / 256, 256>>>(k2_w, WK2H, C2, C2);
    permpack3_kernel<<<(31104 + 255) / 256, 256>>>(k4_w, WK4H, 18, C2);
    packw1_kernel<<<(36864 + 255) / 256, 256>>>(qkv_w, WQKVH, C2, Cc);
    packw1_kernel<<<(18432 + 255) / 256, 256>>>(pw_w, WPWH, Cc, Cc);
    packw1_kernel<<<(18432 + 255) / 256, 256>>>(proj_w, WPROJH, Cc, Cc);
    halfpack4_kernel<<<(384 * 2304 + 255) / 256, 256>>>(x, (uint4*)XH, 384, 2304);

    // 1) qkv 1x1
    conv_mma<1, 4, 0><<<dim3(HW / 128, C2 / 128, Bn), 256>>>(
        WQKVH, XH, QKV1, nullptr, nullptr, nullptr, C2, Cc, Hh, Ww, Hh, Ww, 0);
    // 2) grouped 3x3 (groups=192)
    dwconv2_kernel<<<dim3(9, 192, Bn), 256>>>(QKV1, qkv_conv_w, QKV);
    // 3) cat (fp32 + packed in one pass)
    catpack_kernel<<<(Bn * 192 * 2304 + 255) / 256, 256>>>(QKV, y, CAT, (uint4*)CATH);
    // 4) avg pool 2x2 (packed only)
    poolpack_kernel<<<(Bn * 192 * 576 + 255) / 256, 256>>>(CAT, (uint4*)POOLH);
    // 5) k2 conv 3x3 pad=0 : 48x48 -> 46x46
    conv_mma<3, 4, 0><<<dim3((46 * 46 + 127) / 128, C2 / 128, Bn), 256>>>(
        WK2H, POOLH, K2, nullptr, nullptr, nullptr, C2, C2, 48, 48, 46, 46, 0);
    // 6) k3 conv 3x3 pad=1, fused sigmoid-mul epilogue -> SCH (packed halves)
    conv_mma<3, 4, 1><<<dim3(HW / 128, C2 / 128, Bn), 256>>>(
        WK3H, CATH, SCH, nullptr, CAT, K2, C2, C2, Hh, Ww, Hh, Ww, 1);
    // 7) offset = conv3x3(sc, k4, pad=1), M=18
    conv_mma<3, 1, 0><<<dim3(HW / 128, 1, Bn), 256>>>(
        WK4H, SCH, OFFb, nullptr, nullptr, nullptr, 18, C2, Hh, Ww, Hh, Ww, 1);
    // 8) deformable conv -> packed relu output
    deform_kernel<<<dim3(HW / 128, Gg, Bn), 128>>>(QKV, OFFb, deform_w, deform_b, FEATH);
    // 9) k = 1x1(FEAT) + pw_b
    conv_mma<1, 4, 0><<<dim3(HW / 128, (Cc + 127) / 128, Bn), 256>>>(
        WPWH, FEATH, Kb, pw_b, nullptr, nullptr, Cc, Cc, Hh, Ww, Hh, Ww, 0);
    // 10) row norms
    rownorm_kernel<<<2 * Bn * Cc, 256>>>(QKV, Kb, QN, KN);
    // 11) attention logits + softmax
    attn2_kernel<<<Bn * NH, 256>>>(QKV, Kb, QN, KN, temperature, ATTN);
    // 12) out = attn @ v (packed output)
    attnv_kernel<<<dim3(HW / 256, NH, Bn), 256>>>(ATTN, QKV, AOH);
    // 13) final 1x1 proj -> d_out
    conv_mma<1, 4, 0><<<dim3(HW / 128, (Cc + 127) / 128, Bn), 256>>>(
        WPROJH, AOH, out, nullptr, nullptr, nullptr, Cc, Cc, Hh, Ww, Hh, Ww, 0);
}

// round 16
// speedup vs baseline: 1.0425x; 1.0425x over previous
#include <cuda_runtime.h>
#include <cuda_fp16.h>
#include <math.h>
#include <stdint.h>

// ---------------------------------------------------------------------------
// Problem constants
// ---------------------------------------------------------------------------
#define Bn   4
#define Cc   192
#define C2   384
#define Hh   96
#define Ww   96
#define HW   (Hh*Ww)          // 9216
#define NH   8
#define HD   24
#define Gg   8
#define CG   24

// scratch offsets (in floats / uint32 slots)
#define OFF_QKV1   0ul
#define OFF_QKV    14155776ul
#define OFF_CAT    28311552ul
#define OFF_SC     42467328ul     // 14155776
#define OFF_K2     56623104ul     // 3250176
#define OFF_OFF    59873280ul     // 663552
#define OFF_K      60536832ul     // 7077888
#define OFF_QN     67614720ul
#define OFF_KN     67615488ul
#define OFF_ATTN   67616256ul
#define OFF_WK3H   67634688ul     // 663552
#define OFF_WK2H   68298240ul     // 663552
#define OFF_WK4H   68961792ul     // 31104
#define OFF_WQKVH  68992896ul     // 36864
#define OFF_WPWH   69029760ul     // 18432
#define OFF_WPROJH 69048192ul     // 18432
#define OFF_XH     69066624ul     // 3538944
#define OFF_CATH   72605568ul     // 7077888
#define OFF_POOLH  79683456ul     // 1769472
#define OFF_SCH    81452928ul     // 7077888
#define OFF_FEATH  88530816ul     // 3538944
#define OFF_AOH    92069760ul     // 3538944
#define SCRATCH_TOTAL 95608704ul

__device__ float g_scratch[SCRATCH_TOTAL];

// ---------------------------------------------------------------------------
// helpers
// ---------------------------------------------------------------------------
__device__ __forceinline__ uint32_t pack_h2(float lo, float hi) {
    __half2 h = __floats2half2_rn(lo, hi);
    return *reinterpret_cast<uint32_t*>(&h);
}

__device__ __forceinline__ void mma_16x8x16(float* c, const uint32_t* a,
                                            uint32_t b0, uint32_t b1) {
    asm volatile(
        "mma.sync.aligned.m16n8k16.row.col.f32.f16.f16.f32 "
        "{%0,%1,%2,%3}, {%4,%5,%6,%7}, {%8,%9}, {%0,%1,%2,%3};\n"
        : "+f"(c[0]), "+f"(c[1]), "+f"(c[2]), "+f"(c[3])
        : "r"(a[0]), "r"(a[1]), "r"(a[2]), "r"(a[3]), "r"(b0), "r"(b1));
}

__device__ __forceinline__ void cpasync4(uint32_t saddr, const void* g, bool pred) {
    int sz = pred ? 4 : 0;
    asm volatile("cp.async.ca.shared.global [%0], [%1], 4, %2;\n"
                 :: "r"(saddr), "l"(g), "r"(sz));
}
__device__ __forceinline__ void cpasync16(uint32_t saddr, const void* g) {
    asm volatile("cp.async.cg.shared.global [%0], [%1], 16;\n"
                 :: "r"(saddr), "l"(g));
}
__device__ __forceinline__ void cpasync16ca(uint32_t saddr, const void* g, bool pred) {
    int sz = pred ? 16 : 0;
    asm volatile("cp.async.ca.shared.global [%0], [%1], 16, %2;\n"
                 :: "r"(saddr), "l"(g), "r"(sz));
}
#define CP_COMMIT() asm volatile("cp.async.commit_group;\n" ::: "memory")
#define CP_WAIT0()  asm volatile("cp.async.wait_group 0;\n" ::: "memory")

// ---------------------------------------------------------------------------
// 3x3 weights: permute to tap-major K AND pack half2 K-pairs.
// ---------------------------------------------------------------------------
__global__ void permpack3_kernel(const float* __restrict__ W,
                                 uint32_t* __restrict__ Wph, int M, int Cin)
{
    int K2 = Cin * 9 / 2;
    int i = blockIdx.x * 256 + threadIdx.x;
    if (i >= M * K2) return;
    int m = i / K2;
    int r = i - m * K2;
    int t  = r / (Cin / 2);
    int ic = 2 * (r - t * (Cin / 2));
    float lo = W[(size_t)m * Cin * 9 + ic * 9 + t];
    float hi = W[(size_t)m * Cin * 9 + (ic + 1) * 9 + t];
    Wph[i] = pack_h2(lo, hi);
}

// 1x1 weights: pack half2 K-pairs
__global__ void packw1_kernel(const float* __restrict__ W,
                              uint32_t* __restrict__ Wph, int M, int K)
{
    int K2 = K / 2;
    int i = blockIdx.x * 256 + threadIdx.x;
    if (i >= M * K2) return;
    int m = i / K2;
    int kp = i - m * K2;
    Wph[i] = pack_h2(W[(size_t)m * K + 2 * kp], W[(size_t)m * K + 2 * kp + 1]);
}

// fp32 [2P][4*N4] -> half2 channel-pair packed (external input x only)
__global__ void halfpack4_kernel(const float* __restrict__ X,
                                 uint4* __restrict__ Xp, int P, int N4)
{
    int i = blockIdx.x * 256 + threadIdx.x;
    if (i >= P * N4) return;
    int pr = i / N4, n4 = i - pr * N4;
    float4 a = reinterpret_cast<const float4*>(X)[(size_t)(2 * pr) * N4 + n4];
    float4 b = reinterpret_cast<const float4*>(X)[(size_t)(2 * pr + 1) * N4 + n4];
    uint4 o;
    o.x = pack_h2(a.x, b.x);
    o.y = pack_h2(a.y, b.y);
    o.z = pack_h2(a.z, b.z);
    o.w = pack_h2(a.w, b.w);
    Xp[i] = o;
}

// ---------------------------------------------------------------------------
// fp16 tensor-core implicit-GEMM conv, BK=32 (round-14 proven config).
// ---------------------------------------------------------------------------
template<int KS, int FM>
__global__ __launch_bounds__(256)
void conv_mma(const uint32_t* __restrict__ Wph,
              const uint32_t* __restrict__ Xp,
              float* __restrict__ Y,
              const float* __restrict__ bias,
              int M, int Cin, int IH, int IW,
              int OH, int OW, int pad)
{
    constexpr int BM    = 32 * FM;
    constexpr int BK    = 32;
    constexpr int ASTR  = 20;
    constexpr int B2STR = 136;
    constexpr int ACP   = BM * 4;
    constexpr int AIT   = (ACP + 255) / 256;

    __shared__ uint32_t As2[2][BM * ASTR];
    __shared__ uint32_t Bs2[2][16 * B2STR];

    const int N   = OH * OW;
    const int K   = Cin * KS * KS;
    const int K2  = K >> 1;
    const int IHW = IH * IW;
    const int bz  = blockIdx.z;
    const int m0  = blockIdx.y * BM;
    const int n0  = blockIdx.x * 128;

    const int tid  = threadIdx.x;
    const int wid  = tid >> 5;
    const int lane = tid & 31;
    const int wm   = wid & 1;
    const int wn   = wid >> 1;
    const int mbase = wm * (16 * FM);
    const int nbase = wn * 32;
    const int lg = lane >> 2;
    const int lt = lane & 3;

    const uint32_t* Xb = Xp + (size_t)bz * (Cin >> 1) * IHW;

    float acc[FM][4][4];
    #pragma unroll
    for (int f = 0; f < FM; ++f)
        #pragma unroll
        for (int nf = 0; nf < 4; ++nf)
            #pragma unroll
            for (int r = 0; r < 4; ++r) acc[f][nf][r] = 0.f;

    const int bn = tid & 127;
    const int gn = n0 + bn;
    const bool nvalid = gn < N;
    int oy = 0, ox = 0;
    if (KS == 3) { int g = nvalid ? gn : 0; oy = g / OW; ox = g - oy * OW; }

    auto issueA = [&](int k0, int buf) {
        #pragma unroll
        for (int r = 0; r < AIT; ++r) {
            int idx = tid + 256 * r;
            if (ACP >= 256 * (r + 1) || idx < ACP) {
                int m = idx >> 2;
                int q = idx & 3;
                int gm = m0 + m;
                uint32_t s = (uint32_t)__cvta_generic_to_shared(
                    &As2[buf][m * ASTR + q * 4]);
                cpasync16ca(s, Wph + (size_t)gm * K2 + (k0 >> 1) + q * 4, gm < M);
            }
        }
    };
    auto issueB = [&](int k0, int buf) {
        if (KS == 1) {
            #pragma unroll
            for (int r = 0; r < 2; ++r) {
                int idx = tid + 256 * r;
                int row = idx >> 5;
                int c4  = (idx & 31) * 4;
                uint32_t s = (uint32_t)__cvta_generic_to_shared(&Bs2[buf][row * B2STR + c4]);
                cpasync16(s, Xb + (size_t)((k0 >> 1) + row) * N + n0 + c4);
            }
        } else {
            int tp  = k0 / Cin;
            int icb = k0 - tp * Cin;
            int tdy = (tp >= 6) ? 2 : ((tp >= 3) ? 1 : 0);
            int tdx = tp - 3 * tdy;
            int iy  = oy + tdy - pad;
            int ix  = ox + tdx - pad;
            bool ok = nvalid && iy >= 0 && iy < IH && ix >= 0 && ix < IW;
            const uint32_t* base = Xb + (size_t)(icb >> 1) * IHW + iy * IW + ix;
            #pragma unroll
            for (int r = 0; r < 8; ++r) {
                int kp = (tid >> 7) + 2 * r;
                uint32_t s = (uint32_t)__cvta_generic_to_shared(&Bs2[buf][kp * B2STR + bn]);
                cpasync4(s, base + (size_t)kp * IHW, ok);
            }
        }
    };
    auto compute = [&](int buf) {
        #pragma unroll
        for (int ks = 0; ks < 2; ++ks) {
            const int kb = ks * 8;
            uint32_t a[FM][4];
            #pragma unroll
            for (int f = 0; f < FM; ++f) {
                int mr = mbase + f * 16 + lg;
                a[f][0] = As2[buf][mr * ASTR + kb + lt];
                a[f][1] = As2[buf][(mr + 8) * ASTR + kb + lt];
                a[f][2] = As2[buf][mr * ASTR + kb + lt + 4];
                a[f][3] = As2[buf][(mr + 8) * ASTR + kb + lt + 4];
            }
            #pragma unroll
            for (int nf = 0; nf < 4; ++nf) {
                int nc = nbase + nf * 8 + lg;
                uint32_t b0 = Bs2[buf][(kb + lt) * B2STR + nc];
                uint32_t b1 = Bs2[buf][(kb + lt + 4) * B2STR + nc];
                #pragma unroll
                for (int f = 0; f < FM; ++f)
                    mma_16x8x16(acc[f][nf], a[f], b0, b1);
            }
        }
    };

    const int kTiles = K / BK;
    issueA(0, 0); issueB(0, 0); CP_COMMIT();
    CP_WAIT0(); __syncthreads();

    for (int t = 0; t < kTiles; ++t) {
        if (t + 1 < kTiles) {
            issueA((t + 1) * BK, (t + 1) & 1);
            issueB((t + 1) * BK, (t + 1) & 1);
            CP_COMMIT();
        }
        compute(t & 1);
        if (t + 1 < kTiles) {
            CP_WAIT0(); __syncthreads();
        }
    }

    // ---- epilogue ----
    #pragma unroll
    for (int f = 0; f < FM; ++f) {
        int r0 = m0 + mbase + f * 16 + lg;
        #pragma unroll
        for (int nf = 0; nf < 4; ++nf) {
            int cb = n0 + nbase + nf * 8 + 2 * lt;
            #pragma unroll
            for (int rr = 0; rr < 2; ++rr) {
                int m = r0 + rr * 8;
                if (m >= M) continue;
                float bval = bias ? bias[m] : 0.f;
                #pragma unroll
                for (int cc = 0; cc < 2; ++cc) {
                    int n = cb + cc;
                    if (n >= N) continue;
                    Y[((size_t)bz * M + m) * N + n] = acc[f][nf][rr * 2 + cc] + bval;
                }
            }
        }
    }
}

// ---------------------------------------------------------------------------
// grouped 3x3 conv, smem-tiled
// ---------------------------------------------------------------------------
__global__ __launch_bounds__(256)
void dwconv2_kernel(const float* __restrict__ X,
                    const float* __restrict__ W,
                    float* __restrict__ Y)
{
    __shared__ float xs[2][34][35];
    __shared__ float ws[36];

    const int tile = blockIdx.x;
    const int g    = blockIdx.y;
    const int b    = blockIdx.z;
    const int ty0  = (tile / 3) * 32;
    const int tx0  = (tile % 3) * 32;
    const int tid  = threadIdx.x;

    if (tid < 36) ws[tid] = W[(size_t)g * 36 + tid];

    for (int e = tid; e < 2 * 34 * 34; e += 256) {
        int c  = e / (34 * 34);
        int r  = e - c * 34 * 34;
        int yy = r / 34, xx = r - yy * 34;
        int gy = ty0 + yy - 1, gx = tx0 + xx - 1;
        float v = 0.f;
        if (gy >= 0 && gy < Hh && gx >= 0 && gx < Ww)
            v = X[((size_t)b * C2 + 2 * g + c) * HW + gy * Ww + gx];
        xs[c][yy][xx] = v;
    }
    __syncthreads();

    const int x  = tid & 31;
    const int yb = (tid >> 5) * 4;
    #pragma unroll
    for (int j = 0; j < 4; ++j) {
        int y = yb + j;
        float a0 = 0.f, a1 = 0.f;
        #pragma unroll
        for (int c = 0; c < 2; ++c)
            #pragma unroll
            for (int ky = 0; ky < 3; ++ky)
                #pragma unroll
                for (int kx = 0; kx < 3; ++kx) {
                    float v = xs[c][y + ky][x + kx];
                    a0 += v * ws[c * 9 + ky * 3 + kx];
                    a1 += v * ws[18 + c * 9 + ky * 3 + kx];
                }
        size_t o = ((size_t)b * C2 + 2 * g) * HW + (ty0 + y) * Ww + tx0 + x;
        Y[o]      = a0;
        Y[o + HW] = a1;
    }
}

// cat: channel-pair thread; writes CAT fp32 + CATH packed in one pass.
__global__ void catpack_kernel(const float* __restrict__ QKV,
                               const float* __restrict__ Yin,
                               float* __restrict__ CAT,
                               uint4* __restrict__ CATH)
{
    const int NP = C2 / 2;
    const int N4 = HW / 4;
    int i = blockIdx.x * 256 + threadIdx.x;
    if (i >= Bn * NP * N4) return;
    int p4 = i % N4;
    int pr = (i / N4) % NP;
    int b  = i / (N4 * NP);
    int c0 = 2 * pr;
    float4 a, bv;
    if (c0 < Cc) {
        a  = reinterpret_cast<const float4*>(QKV + ((size_t)b * C2 + c0) * HW)[p4];
        bv = reinterpret_cast<const float4*>(QKV + ((size_t)b * C2 + c0 + 1) * HW)[p4];
    } else {
        a  = reinterpret_cast<const float4*>(Yin + ((size_t)b * Cc + (c0 - Cc)) * HW)[p4];
        bv = reinterpret_cast<const float4*>(Yin + ((size_t)b * Cc + (c0 - Cc) + 1) * HW)[p4];
    }
    reinterpret_cast<float4*>(CAT + ((size_t)b * C2 + c0) * HW)[p4]     = a;
    reinterpret_cast<float4*>(CAT + ((size_t)b * C2 + c0 + 1) * HW)[p4] = bv;
    uint4 o;
    o.x = pack_h2(a.x, bv.x);
    o.y = pack_h2(a.y, bv.y);
    o.z = pack_h2(a.z, bv.z);
    o.w = pack_h2(a.w, bv.w);
    CATH[((size_t)b * NP + pr) * N4 + p4] = o;
}

// 2x2 avg pool, packed-only output
__global__ void poolpack_kernel(const float* __restrict__ X, uint4* __restrict__ Yp)
{
    const int NP   = C2 / 2;
    const int OHW4 = 48 * 48 / 4;
    int i = blockIdx.x * 256 + threadIdx.x;
    if (i >= Bn * NP * OHW4) return;
    int r  = i % OHW4;
    int pr = (i / OHW4) % NP;
    int b  = i / (OHW4 * NP);
    int y  = r / 12;
    int x8 = (r % 12) * 8;
    float pv[2][4];
    #pragma unroll
    for (int c = 0; c < 2; ++c) {
        const float* xp = X + ((size_t)b * C2 + 2 * pr + c) * HW;
        float4 r0a = *reinterpret_cast<const float4*>(xp + (2 * y) * Ww + x8);
        float4 r0b = *reinterpret_cast<const float4*>(xp + (2 * y) * Ww + x8 + 4);
        float4 r1a = *reinterpret_cast<const float4*>(xp + (2 * y + 1) * Ww + x8);
        float4 r1b = *reinterpret_cast<const float4*>(xp + (2 * y + 1) * Ww + x8 + 4);
        pv[c][0] = (r0a.x + r0a.y + r1a.x + r1a.y) * 0.25f;
        pv[c][1] = (r0a.z + r0a.w + r1a.z + r1a.w) * 0.25f;
        pv[c][2] = (r0b.x + r0b.y + r1b.x + r1b.y) * 0.25f;
        pv[c][3] = (r0b.z + r0b.w + r1b.z + r1b.w) * 0.25f;
    }
    uint4 o;
    o.x = pack_h2(pv[0][0], pv[1][0]);
    o.y = pack_h2(pv[0][1], pv[1][1]);
    o.z = pack_h2(pv[0][2], pv[1][2]);
    o.w = pack_h2(pv[0][3], pv[1][3]);
    Yp[((size_t)b * NP + pr) * OHW4 + r] = o;
}

// SCH = pack(SC * sigmoid(CAT + upsample(K2)))
__global__ void sigmulpack_kernel(const float* __restrict__ SC,
                                  const float* __restrict__ CAT,
                                  const float* __restrict__ K2,
                                  uint4* __restrict__ SCH)
{
    const int NP = C2 / 2;
    const int N4 = HW / 4;
    int i = blockIdx.x * 256 + threadIdx.x;
    if (i >= Bn * NP * N4) return;
    int p4 = i % N4;
    int pr = (i / N4) % NP;
    int b  = i / (N4 * NP);
    int p  = p4 * 4;
    int y  = p / Ww, x = p % Ww;
    int iy = (y * 46) / 96;
    int ix0 = ((x + 0) * 46) / 96;
    int ix1 = ((x + 1) * 46) / 96;
    int ix2 = ((x + 2) * 46) / 96;
    int ix3 = ((x + 3) * 46) / 96;
    float sv2[2][4];
    #pragma unroll
    for (int c = 0; c < 2; ++c) {
        size_t bc = (size_t)b * C2 + 2 * pr + c;
        const float* k2r = K2 + bc * (46 * 46) + iy * 46;
        float4 cv = reinterpret_cast<const float4*>(CAT + bc * HW)[p4];
        float4 sv = reinterpret_cast<const float4*>(SC + bc * HW)[p4];
        sv2[c][0] = sv.x / (1.f + expf(-(cv.x + k2r[ix0])));
        sv2[c][1] = sv.y / (1.f + expf(-(cv.y + k2r[ix1])));
        sv2[c][2] = sv.z / (1.f + expf(-(cv.z + k2r[ix2])));
        sv2[c][3] = sv.w / (1.f + expf(-(cv.w + k2r[ix3])));
    }
    uint4 o;
    o.x = pack_h2(sv2[0][0], sv2[1][0]);
    o.y = pack_h2(sv2[0][1], sv2[1][1]);
    o.z = pack_h2(sv2[0][2], sv2[1][2]);
    o.w = pack_h2(sv2[0][3], sv2[1][3]);
    SCH[((size_t)b * NP + pr) * N4 + p4] = o;
}

// ---------------------------------------------------------------------------
// fused deformable conv; float4 weight LDS; writes packed half2 relu output.
// ---------------------------------------------------------------------------
__global__ __launch_bounds__(128)
void deform_kernel(const float* __restrict__ Q,
                   const float* __restrict__ OFF,
                   const float* __restrict__ W,
                   const float* __restrict__ Bias,
                   uint32_t* __restrict__ Yp)
{
    __shared__ __align__(16) float ws2[216 * 24];
    const int g = blockIdx.y;
    const int b = blockIdx.z;
    const int tid = threadIdx.x;

    for (int e = tid; e < 216 * 24; e += 128) {
        int it = e / 24;
        int o  = e - it * 24;
        ws2[e] = W[(size_t)(g * CG + o) * 216 + it];
    }
    __syncthreads();

    int p = blockIdx.x * 128 + tid;
    int y = p / Ww, x = p % Ww;
    const float* offb = OFF + (size_t)b * 18 * HW;

    float acc[24];
    #pragma unroll
    for (int o = 0; o < 24; ++o) acc[o] = Bias[g * CG + o];

    const float* qc = Q + ((size_t)b * C2 + g * CG) * HW;

    for (int t = 0; t < 9; ++t) {
        float dy = offb[(size_t)(2 * t) * HW + p];
        float dx = offb[(size_t)(2 * t + 1) * HW + p];
        float m  = 1.f / (1.f + expf(-offb[(size_t)t * HW + p]));
        float py = dy + (float)(y - 1 + t / 3);
        float px = dx + (float)(x - 1 + t % 3);
        float y0f = floorf(py), x0f = floorf(px);
        int   y0 = (int)y0f,    x0 = (int)x0f;
        float fy = py - y0f,    fx = px - x0f;
        float w00 = (1.f - fy) * (1.f - fx);
        float w01 = (1.f - fy) * fx;
        float w10 = fy * (1.f - fx);
        float w11 = fy * fx;
        bool vy0 = (y0 >= 0 && y0 <= Hh - 1), vy1 = (y0 + 1 >= 0 && y0 + 1 <= Hh - 1);
        bool vx0 = (x0 >= 0 && x0 <= Ww - 1), vx1 = (x0 + 1 >= 0 && x0 + 1 <= Ww - 1);
        int cy0 = min(max(y0, 0), Hh - 1),     cy1 = min(max(y0 + 1, 0), Hh - 1);
        int cx0 = min(max(x0, 0), Ww - 1),     cx1 = min(max(x0 + 1, 0), Ww - 1);
        int i00 = cy0 * Ww + cx0, i01 = cy0 * Ww + cx1;
        int i10 = cy1 * Ww + cx0, i11 = cy1 * Ww + cx1;
        w00 = (vy0 && vx0) ? w00 * m : 0.f;
        w01 = (vy0 && vx1) ? w01 * m : 0.f;
        w10 = (vy1 && vx0) ? w10 * m : 0.f;
        w11 = (vy1 && vx1) ? w11 * m : 0.f;

        #pragma unroll
        for (int i = 0; i < 24; ++i) {
            const float* qp = qc + (size_t)i * HW;
            float val = w00 * qp[i00] + w01 * qp[i01] + w10 * qp[i10] + w11 * qp[i11];
            const float4* wr4 = reinterpret_cast<const float4*>(&ws2[(i * 9 + t) * 24]);
            #pragma unroll
            for (int o4 = 0; o4 < 6; ++o4) {
                float4 w4 = wr4[o4];
                acc[4 * o4 + 0] += val * w4.x;
                acc[4 * o4 + 1] += val * w4.y;
                acc[4 * o4 + 2] += val * w4.z;
                acc[4 * o4 + 3] += val * w4.w;
            }
        }
    }
    #pragma unroll
    for (int u = 0; u < 12; ++u) {
        uint32_t v = pack_h2(fmaxf(acc[2 * u], 0.f), fmaxf(acc[2 * u + 1], 0.f));
        Yp[((size_t)b * (Cc / 2) + g * 12 + u) * HW + p] = v;
    }
}

// ---------------------------------------------------------------------------
// row L2 norms (float4)
// ---------------------------------------------------------------------------
__global__ void rownorm_kernel(const float* __restrict__ QKV,
                               const float* __restrict__ Kb,
                               float* __restrict__ QN,
                               float* __restrict__ KN)
{
    int row   = blockIdx.x;
    int which = row / (Bn * Cc);
    row %= (Bn * Cc);
    int b = row / Cc, c = row % Cc;
    const float* src = which ? (Kb + ((size_t)b * Cc + c) * HW)
                             : (QKV + ((size_t)b * C2 + c) * HW);
    float s = 0.f;
    for (int n = threadIdx.x; n < HW / 4; n += 256) {
        float4 v = reinterpret_cast<const float4*>(src)[n];
        s += v.x * v.x + v.y * v.y + v.z * v.z + v.w * v.w;
    }
    __shared__ float sm[256];
    sm[threadIdx.x] = s;
    __syncthreads();
    for (int d = 128; d > 0; d >>= 1) {
        if (threadIdx.x < d) sm[threadIdx.x] += sm[threadIdx.x + d];
        __syncthreads();
    }
    if (threadIdx.x == 0) {
        float nrm = fmaxf(sqrtf(sm[0]), 1e-12f);
        (which ? KN : QN)[b * Cc + c] = nrm;
    }
}

// ---------------------------------------------------------------------------
// attention: one block per (b,h).  K-head staged through smem.
// ---------------------------------------------------------------------------
#define CNK 384
__global__ __launch_bounds__(256)
void attn2_kernel(const float* __restrict__ QKV,
                  const float* __restrict__ Kb,
                  const float* __restrict__ QN,
                  const float* __restrict__ KN,
                  const float* __restrict__ TEMP,
                  float* __restrict__ ATTN)
{
    __shared__ float ks_[24][CNK + 8];
    __shared__ float logits[24][24];

    const int b = blockIdx.x >> 3;
    const int h = blockIdx.x & 7;
    const int tid  = threadIdx.x;
    const int wid  = tid >> 5;
    const int lane = tid & 31;

    const float* qh = QKV + ((size_t)b * C2 + h * HD) * HW;
    const float* kh = Kb  + ((size_t)b * Cc + h * HD) * HW;

    float acc[3][24];
    #pragma unroll
    for (int r = 0; r < 3; ++r)
        #pragma unroll
        for (int j = 0; j < 24; ++j) acc[r][j] = 0.f;

    const float* q0p = qh + (size_t)(3 * wid + 0) * HW;
    const float* q1p = qh + (size_t)(3 * wid + 1) * HW;
    const float* q2p = qh + (size_t)(3 * wid + 2) * HW;

    for (int n0 = 0; n0 < HW; n0 += CNK) {
        __syncthreads();
        for (int e = tid; e < 24 * (CNK / 4); e += 256) {
            int j = e / (CNK / 4);
            int c = e - j * (CNK / 4);
            float4 v = *reinterpret_cast<const float4*>(kh + (size_t)j * HW + n0 + c * 4);
            ks_[j][c * 4 + 0] = v.x;
            ks_[j][c * 4 + 1] = v.y;
            ks_[j][c * 4 + 2] = v.z;
            ks_[j][c * 4 + 3] = v.w;
        }
        __syncthreads();

        for (int i = lane; i < CNK; i += 32) {
            int n = n0 + i;
            float q0 = q0p[n], q1 = q1p[n], q2 = q2p[n];
            #pragma unroll
            for (int j = 0; j < 24; ++j) {
                float kv = ks_[j][i];
                acc[0][j] += q0 * kv;
                acc[1][j] += q1 * kv;
                acc[2][j] += q2 * kv;
            }
        }
    }

    #pragma unroll
    for (int r = 0; r < 3; ++r)
        #pragma unroll
        for (int j = 0; j < 24; ++j) {
            float v = acc[r][j];
            for (int o = 16; o > 0; o >>= 1) v += __shfl_down_sync(0xffffffffu, v, o);
            if (lane == 0) logits[wid * 3 + r][j] = v;
        }
    __syncthreads();

    if (tid < 24) {
        int i = tid;
        float qn = QN[b * Cc + h * HD + i];
        float tp = TEMP[h];
        float s[24];
        float mx = -1e30f;
        #pragma unroll
        for (int j = 0; j < 24; ++j) {
            s[j] = logits[i][j] / (qn * KN[b * Cc + h * HD + j]) * tp;
            mx = fmaxf(mx, s[j]);
        }
        float sum = 0.f;
        #pragma unroll
        for (int j = 0; j < 24; ++j) { s[j] = expf(s[j] - mx); sum += s[j]; }
        float inv = 1.f / sum;
        #pragma unroll
        for (int j = 0; j < 24; ++j)
            ATTN[(((size_t)b * NH + h) * HD + i) * HD + j] = s[j] * inv;
    }
}

// out = attn @ v ; writes packed half2 directly
__global__ void attnv_kernel(const float* __restrict__ ATTN,
                             const float* __restrict__ QKV,
                             uint32_t* __restrict__ AOp)
{
    int h = blockIdx.y, b = blockIdx.z;
    int n = blockIdx.x * 256 + threadIdx.x;
    __shared__ float a_s[HD * HD];
    for (int e = threadIdx.x; e < HD * HD; e += 256)
        a_s[e] = ATTN[((size_t)b * NH + h) * HD * HD + e];
    __syncthreads();
    const float* vb = QKV + ((size_t)b * C2 + Cc + h * HD) * HW;
    float acc[HD] = {};
    #pragma unroll
    for (int j = 0; j < HD; ++j) {
        float vv = vb[(size_t)j * HW + n];
        #pragma unroll
        for (int i = 0; i < HD; ++i) acc[i] += a_s[i * HD + j] * vv;
    }
    #pragma unroll
    for (int u = 0; u < HD / 2; ++u)
        AOp[((size_t)b * (Cc / 2) + h * (HD / 2) + u) * HW + n] =
            pack_h2(acc[2 * u], acc[2 * u + 1]);
}

// ---------------------------------------------------------------------------
// launcher
// ---------------------------------------------------------------------------
extern "C" void kernel_launch(void* const* d_in, const int* in_sizes, int n_in,
                              void* d_out, int out_size)
{
    const float* x           = (const float*)d_in[0];
    const float* y           = (const float*)d_in[1];
    const float* temperature = (const float*)d_in[2];
    const float* qkv_w       = (const float*)d_in[3];
    const float* qkv_conv_w  = (const float*)d_in[4];
    const float* proj_w      = (const float*)d_in[5];
    const float* k2_w        = (const float*)d_in[6];
    const float* k3_w        = (const float*)d_in[7];
    const float* k4_w        = (const float*)d_in[8];
    const float* deform_w    = (const float*)d_in[9];
    const float* deform_b    = (const float*)d_in[10];
    const float* pw_w        = (const float*)d_in[11];
    const float* pw_b        = (const float*)d_in[12];
    float* out = (float*)d_out;

    float* S = nullptr;
    cudaGetSymbolAddress((void**)&S, g_scratch);
    float* QKV1 = S + OFF_QKV1;
    float* QKV  = S + OFF_QKV;
    float* CAT  = S + OFF_CAT;
    float* SC   = S + OFF_SC;
    float* K2   = S + OFF_K2;
    float* OFFb = S + OFF_OFF;
    float* Kb   = S + OFF_K;
    float* QN   = S + OFF_QN;
    float* KN   = S + OFF_KN;
    float* ATTN = S + OFF_ATTN;
    uint32_t* WK3H   = (uint32_t*)(S + OFF_WK3H);
    uint32_t* WK2H   = (uint32_t*)(S + OFF_WK2H);
    uint32_t* WK4H   = (uint32_t*)(S + OFF_WK4H);
    uint32_t* WQKVH  = (uint32_t*)(S + OFF_WQKVH);
    uint32_t* WPWH   = (uint32_t*)(S + OFF_WPWH);
    uint32_t* WPROJH = (uint32_t*)(S + OFF_WPROJH);
    uint32_t* XH    = (uint32_t*)(S + OFF_XH);
    uint32_t* CATH  = (uint32_t*)(S + OFF_CATH);
    uint32_t* POOLH = (uint32_t*)(S + OFF_POOLH);
    uint32_t* SCH   = (uint32_t*)(S + OFF_SCH);
    uint32_t* FEATH = (uint32_t*)(S + OFF_FEATH);
    uint32_t* AOH   = (uint32_t*)(S + OFF_AOH);

    // 0) weight permute+pack, 1x1 weight pack, pack x
    permpack3_kernel<<<(663552 + 255) / 256, 256>>>(k3_w, WK3H, C2, C2);
    permpack3_kernel<<<(663552 + 255) / 256, 256>>>(k2_w, WK2H, C2, C2);
    permpack3_kernel<<<(31104 + 255) / 256, 256>>>(k4_w, WK4H, 18, C2);
    packw1_kernel<<<(36864 + 255) / 256, 256>>>(qkv_w, WQKVH, C2, Cc);
    packw1_kernel<<<(18432 + 255) / 256, 256>>>(pw_w, WPWH, Cc, Cc);
    packw1_kernel<<<(18432 + 255) / 256, 256>>>(proj_w, WPROJH, Cc, Cc);
    halfpack4_kernel<<<(384 * 2304 + 255) / 256, 256>>>(x, (uint4*)XH, 384, 2304);

    // 1) qkv 1x1
    conv_mma<1, 4><<<dim3(HW / 128, C2 / 128, Bn), 256>>>(
        WQKVH, XH, QKV1, nullptr, C2, Cc, Hh, Ww, Hh, Ww, 0);
    // 2) grouped 3x3 (groups=192)
    dwconv2_kernel<<<dim3(9, 192, Bn), 256>>>(QKV1, qkv_conv_w, QKV);
    // 3) cat (fp32 + packed in one pass)
    catpack_kernel<<<(Bn * 192 * 2304 + 255) / 256, 256>>>(QKV, y, CAT, (uint4*)CATH);
    // 4) k3 conv 3x3 pad=1
    conv_mma<3, 4><<<dim3(HW / 128, C2 / 128, Bn), 256>>>(
        WK3H, CATH, SC, nullptr, C2, C2, Hh, Ww, Hh, Ww, 1);
    // 5) avg pool 2x2 (packed only)
    poolpack_kernel<<<(Bn * 192 * 576 + 255) / 256, 256>>>(CAT, (uint4*)POOLH);
    // 6) k2 conv 3x3 pad=0 : 48x48 -> 46x46
    conv_mma<3, 4><<<dim3((46 * 46 + 127) / 128, C2 / 128, Bn), 256>>>(
        WK2H, POOLH, K2, nullptr, C2, C2, 48, 48, 46, 46, 0);
    // 7) SCH = pack(SC * sigmoid(CAT + upsample(K2)))
    sigmulpack_kernel<<<(Bn * 192 * 2304 + 255) / 256, 256>>>(SC, CAT, K2, (uint4*)SCH);
    // 8) offset = conv3x3(sc, k4, pad=1), M=18
    conv_mma<3, 1><<<dim3(HW / 128, 1, Bn), 256>>>(
        WK4H, SCH, OFFb, nullptr, 18, C2, Hh, Ww, Hh, Ww, 1);
    // 9) deformable conv -> packed relu output
    deform_kernel<<<dim3(HW / 128, Gg, Bn), 128>>>(QKV, OFFb, deform_w, deform_b, FEATH);
    // 10) k = 1x1(FEAT) + pw_b
    conv_mma<1, 4><<<dim3(HW / 128, (Cc + 127) / 128, Bn), 256>>>(
        WPWH, FEATH, Kb, pw_b, Cc, Cc, Hh, Ww, Hh, Ww, 0);
    // 11) row norms
    rownorm_kernel<<<2 * Bn * Cc, 256>>>(QKV, Kb, QN, KN);
    // 12) attention logits + softmax
    attn2_kernel<<<Bn * NH, 256>>>(QKV, Kb, QN, KN, temperature, ATTN);
    // 13) out = attn @ v (packed output)
    attnv_kernel<<<dim3(HW / 256, NH, Bn), 256>>>(ATTN, QKV, AOH);
    // 14) final 1x1 proj -> d_out
    conv_mma<1, 4><<<dim3(HW / 128, (Cc + 127) / 128, Bn), 256>>>(
        WPROJH, AOH, out, nullptr, Cc, Cc, Hh, Ww, Hh, Ww, 0);
}

// round 17
// speedup vs baseline: 1.0508x; 1.0080x over previous
#include <cuda_runtime.h>
#include <cuda_fp16.h>
#include <math.h>
#include <stdint.h>

// ---------------------------------------------------------------------------
// Problem constants
// ---------------------------------------------------------------------------
#define Bn   4
#define Cc   192
#define C2   384
#define Hh   96
#define Ww   96
#define HW   (Hh*Ww)          // 9216
#define NH   8
#define HD   24
#define Gg   8
#define CG   24

// scratch offsets (in floats / uint32 slots)
#define OFF_QKV1   0ul
#define OFF_QKV    14155776ul
#define OFF_CAT    28311552ul
#define OFF_SC     42467328ul     // 14155776
#define OFF_K2     56623104ul     // 3250176
#define OFF_OFF    59873280ul     // 663552
#define OFF_K      60536832ul     // 7077888
#define OFF_QN     67614720ul
#define OFF_KN     67615488ul
#define OFF_ATTN   67616256ul
#define OFF_WK3H   67634688ul     // 663552
#define OFF_WK2H   68298240ul     // 663552
#define OFF_WK4H   68961792ul     // 31104
#define OFF_WQKVH  68992896ul     // 36864
#define OFF_WPWH   69029760ul     // 18432
#define OFF_WPROJH 69048192ul     // 18432
#define OFF_XH     69066624ul     // 3538944
#define OFF_CATH   72605568ul     // 7077888
#define OFF_POOLH  79683456ul     // 1769472
#define OFF_SCH    81452928ul     // 7077888
#define OFF_FEATH  88530816ul     // 3538944
#define OFF_AOH    92069760ul     // 3538944
#define SCRATCH_TOTAL 95608704ul

__device__ float g_scratch[SCRATCH_TOTAL];

// ---------------------------------------------------------------------------
// helpers
// ---------------------------------------------------------------------------
__device__ __forceinline__ uint32_t pack_h2(float lo, float hi) {
    __half2 h = __floats2half2_rn(lo, hi);
    return *reinterpret_cast<uint32_t*>(&h);
}

__device__ __forceinline__ void mma_16x8x16(float* c, const uint32_t* a,
                                            uint32_t b0, uint32_t b1) {
    asm volatile(
        "mma.sync.aligned.m16n8k16.row.col.f32.f16.f16.f32 "
        "{%0,%1,%2,%3}, {%4,%5,%6,%7}, {%8,%9}, {%0,%1,%2,%3};\n"
        : "+f"(c[0]), "+f"(c[1]), "+f"(c[2]), "+f"(c[3])
        : "r"(a[0]), "r"(a[1]), "r"(a[2]), "r"(a[3]), "r"(b0), "r"(b1));
}

__device__ __forceinline__ void cpasync4(uint32_t saddr, const void* g, bool pred) {
    int sz = pred ? 4 : 0;
    asm volatile("cp.async.ca.shared.global [%0], [%1], 4, %2;\n"
                 :: "r"(saddr), "l"(g), "r"(sz));
}
__device__ __forceinline__ void cpasync16(uint32_t saddr, const void* g) {
    asm volatile("cp.async.cg.shared.global [%0], [%1], 16;\n"
                 :: "r"(saddr), "l"(g));
}
__device__ __forceinline__ void cpasync16ca(uint32_t saddr, const void* g, bool pred) {
    int sz = pred ? 16 : 0;
    asm volatile("cp.async.ca.shared.global [%0], [%1], 16, %2;\n"
                 :: "r"(saddr), "l"(g), "r"(sz));
}
#define CP_COMMIT() asm volatile("cp.async.commit_group;\n" ::: "memory")
#define CP_WAIT0()  asm volatile("cp.async.wait_group 0;\n" ::: "memory")

// ---------------------------------------------------------------------------
// merged prep: all weight permute/packs + x halfpack in ONE launch.
// segments (element index ranges, exact):
//   [0,663552)            k3 permpack (M=384,Cin=384)
//   [663552,1327104)      k2 permpack
//   [1327104,1358208)     k4 permpack (M=18)
//   [1358208,1395072)     qkv packw1  (M=384,K=192)
//   [1395072,1413504)     pw packw1   (M=192,K=192)
//   [1413504,1431936)     proj packw1 (M=192,K=192)
//   [1431936,2316672)     x halfpack  (P=384,N4=2304, uint4 elements)
// ---------------------------------------------------------------------------
__device__ __forceinline__ void permpack3_body(const float* __restrict__ W,
                                               uint32_t* __restrict__ Wph,
                                               int Cin, int i)
{
    int K2 = Cin * 9 / 2;
    int m = i / K2;
    int r = i - m * K2;
    int t  = r / (Cin / 2);
    int ic = 2 * (r - t * (Cin / 2));
    float lo = W[(size_t)m * Cin * 9 + ic * 9 + t];
    float hi = W[(size_t)m * Cin * 9 + (ic + 1) * 9 + t];
    Wph[i] = pack_h2(lo, hi);
}

__device__ __forceinline__ void packw1_body(const float* __restrict__ W,
                                            uint32_t* __restrict__ Wph,
                                            int K, int i)
{
    int K2 = K / 2;
    int m = i / K2;
    int kp = i - m * K2;
    Wph[i] = pack_h2(W[(size_t)m * K + 2 * kp], W[(size_t)m * K + 2 * kp + 1]);
}

__global__ void prep_kernel(const float* __restrict__ k3_w,
                            const float* __restrict__ k2_w,
                            const float* __restrict__ k4_w,
                            const float* __restrict__ qkv_w,
                            const float* __restrict__ pw_w,
                            const float* __restrict__ proj_w,
                            const float* __restrict__ x,
                            uint32_t* __restrict__ WK3H,
                            uint32_t* __restrict__ WK2H,
                            uint32_t* __restrict__ WK4H,
                            uint32_t* __restrict__ WQKVH,
                            uint32_t* __restrict__ WPWH,
                            uint32_t* __restrict__ WPROJH,
                            uint4* __restrict__ XH)
{
    int i = blockIdx.x * 256 + threadIdx.x;
    if (i < 663552) {
        permpack3_body(k3_w, WK3H, C2, i);
    } else if (i < 1327104) {
        permpack3_body(k2_w, WK2H, C2, i - 663552);
    } else if (i < 1358208) {
        permpack3_body(k4_w, WK4H, C2, i - 1327104);
    } else if (i < 1395072) {
        packw1_body(qkv_w, WQKVH, Cc, i - 1358208);
    } else if (i < 1413504) {
        packw1_body(pw_w, WPWH, Cc, i - 1395072);
    } else if (i < 1431936) {
        packw1_body(proj_w, WPROJH, Cc, i - 1413504);
    } else if (i < 2316672) {
        int e = i - 1431936;
        const int N4 = HW / 4;
        int pr = e / N4, n4 = e - pr * N4;
        float4 a = reinterpret_cast<const float4*>(x)[(size_t)(2 * pr) * N4 + n4];
        float4 b = reinterpret_cast<const float4*>(x)[(size_t)(2 * pr + 1) * N4 + n4];
        uint4 o;
        o.x = pack_h2(a.x, b.x);
        o.y = pack_h2(a.y, b.y);
        o.z = pack_h2(a.z, b.z);
        o.w = pack_h2(a.w, b.w);
        XH[e] = o;
    }
}

// ---------------------------------------------------------------------------
// fp16 tensor-core implicit-GEMM conv, BK=32 (round-14/16 proven config).
// ---------------------------------------------------------------------------
template<int KS, int FM>
__global__ __launch_bounds__(256)
void conv_mma(const uint32_t* __restrict__ Wph,
              const uint32_t* __restrict__ Xp,
              float* __restrict__ Y,
              const float* __restrict__ bias,
              int M, int Cin, int IH, int IW,
              int OH, int OW, int pad)
{
    constexpr int BM    = 32 * FM;
    constexpr int BK    = 32;
    constexpr int ASTR  = 20;
    constexpr int B2STR = 136;
    constexpr int ACP   = BM * 4;
    constexpr int AIT   = (ACP + 255) / 256;

    __shared__ uint32_t As2[2][BM * ASTR];
    __shared__ uint32_t Bs2[2][16 * B2STR];

    const int N   = OH * OW;
    const int K   = Cin * KS * KS;
    const int K2  = K >> 1;
    const int IHW = IH * IW;
    const int bz  = blockIdx.z;
    const int m0  = blockIdx.y * BM;
    const int n0  = blockIdx.x * 128;

    const int tid  = threadIdx.x;
    const int wid  = tid >> 5;
    const int lane = tid & 31;
    const int wm   = wid & 1;
    const int wn   = wid >> 1;
    const int mbase = wm * (16 * FM);
    const int nbase = wn * 32;
    const int lg = lane >> 2;
    const int lt = lane & 3;

    const uint32_t* Xb = Xp + (size_t)bz * (Cin >> 1) * IHW;

    float acc[FM][4][4];
    #pragma unroll
    for (int f = 0; f < FM; ++f)
        #pragma unroll
        for (int nf = 0; nf < 4; ++nf)
            #pragma unroll
            for (int r = 0; r < 4; ++r) acc[f][nf][r] = 0.f;

    const int bn = tid & 127;
    const int gn = n0 + bn;
    const bool nvalid = gn < N;
    int oy = 0, ox = 0;
    if (KS == 3) { int g = nvalid ? gn : 0; oy = g / OW; ox = g - oy * OW; }

    auto issueA = [&](int k0, int buf) {
        #pragma unroll
        for (int r = 0; r < AIT; ++r) {
            int idx = tid + 256 * r;
            if (ACP >= 256 * (r + 1) || idx < ACP) {
                int m = idx >> 2;
                int q = idx & 3;
                int gm = m0 + m;
                uint32_t s = (uint32_t)__cvta_generic_to_shared(
                    &As2[buf][m * ASTR + q * 4]);
                cpasync16ca(s, Wph + (size_t)gm * K2 + (k0 >> 1) + q * 4, gm < M);
            }
        }
    };
    auto issueB = [&](int k0, int buf) {
        if (KS == 1) {
            #pragma unroll
            for (int r = 0; r < 2; ++r) {
                int idx = tid + 256 * r;
                int row = idx >> 5;
                int c4  = (idx & 31) * 4;
                uint32_t s = (uint32_t)__cvta_generic_to_shared(&Bs2[buf][row * B2STR + c4]);
                cpasync16(s, Xb + (size_t)((k0 >> 1) + row) * N + n0 + c4);
            }
        } else {
            int tp  = k0 / Cin;
            int icb = k0 - tp * Cin;
            int tdy = (tp >= 6) ? 2 : ((tp >= 3) ? 1 : 0);
            int tdx = tp - 3 * tdy;
            int iy  = oy + tdy - pad;
            int ix  = ox + tdx - pad;
            bool ok = nvalid && iy >= 0 && iy < IH && ix >= 0 && ix < IW;
            const uint32_t* base = Xb + (size_t)(icb >> 1) * IHW + iy * IW + ix;
            #pragma unroll
            for (int r = 0; r < 8; ++r) {
                int kp = (tid >> 7) + 2 * r;
                uint32_t s = (uint32_t)__cvta_generic_to_shared(&Bs2[buf][kp * B2STR + bn]);
                cpasync4(s, base + (size_t)kp * IHW, ok);
            }
        }
    };
    auto compute = [&](int buf) {
        #pragma unroll
        for (int ks = 0; ks < 2; ++ks) {
            const int kb = ks * 8;
            uint32_t a[FM][4];
            #pragma unroll
            for (int f = 0; f < FM; ++f) {
                int mr = mbase + f * 16 + lg;
                a[f][0] = As2[buf][mr * ASTR + kb + lt];
                a[f][1] = As2[buf][(mr + 8) * ASTR + kb + lt];
                a[f][2] = As2[buf][mr * ASTR + kb + lt + 4];
                a[f][3] = As2[buf][(mr + 8) * ASTR + kb + lt + 4];
            }
            #pragma unroll
            for (int nf = 0; nf < 4; ++nf) {
                int nc = nbase + nf * 8 + lg;
                uint32_t b0 = Bs2[buf][(kb + lt) * B2STR + nc];
                uint32_t b1 = Bs2[buf][(kb + lt + 4) * B2STR + nc];
                #pragma unroll
                for (int f = 0; f < FM; ++f)
                    mma_16x8x16(acc[f][nf], a[f], b0, b1);
            }
        }
    };

    const int kTiles = K / BK;
    issueA(0, 0); issueB(0, 0); CP_COMMIT();
    CP_WAIT0(); __syncthreads();

    for (int t = 0; t < kTiles; ++t) {
        if (t + 1 < kTiles) {
            issueA((t + 1) * BK, (t + 1) & 1);
            issueB((t + 1) * BK, (t + 1) & 1);
            CP_COMMIT();
        }
        compute(t & 1);
        if (t + 1 < kTiles) {
            CP_WAIT0(); __syncthreads();
        }
    }

    // ---- epilogue ----
    #pragma unroll
    for (int f = 0; f < FM; ++f) {
        int r0 = m0 + mbase + f * 16 + lg;
        #pragma unroll
        for (int nf = 0; nf < 4; ++nf) {
            int cb = n0 + nbase + nf * 8 + 2 * lt;
            #pragma unroll
            for (int rr = 0; rr < 2; ++rr) {
                int m = r0 + rr * 8;
                if (m >= M) continue;
                float bval = bias ? bias[m] : 0.f;
                #pragma unroll
                for (int cc = 0; cc < 2; ++cc) {
                    int n = cb + cc;
                    if (n >= N) continue;
                    Y[((size_t)bz * M + m) * N + n] = acc[f][nf][rr * 2 + cc] + bval;
                }
            }
        }
    }
}

// ---------------------------------------------------------------------------
// grouped 3x3 conv, smem-tiled
// ---------------------------------------------------------------------------
__global__ __launch_bounds__(256)
void dwconv2_kernel(const float* __restrict__ X,
                    const float* __restrict__ W,
                    float* __restrict__ Y)
{
    __shared__ float xs[2][34][35];
    __shared__ float ws[36];

    const int tile = blockIdx.x;
    const int g    = blockIdx.y;
    const int b    = blockIdx.z;
    const int ty0  = (tile / 3) * 32;
    const int tx0  = (tile % 3) * 32;
    const int tid  = threadIdx.x;

    if (tid < 36) ws[tid] = W[(size_t)g * 36 + tid];

    for (int e = tid; e < 2 * 34 * 34; e += 256) {
        int c  = e / (34 * 34);
        int r  = e - c * 34 * 34;
        int yy = r / 34, xx = r - yy * 34;
        int gy = ty0 + yy - 1, gx = tx0 + xx - 1;
        float v = 0.f;
        if (gy >= 0 && gy < Hh && gx >= 0 && gx < Ww)
            v = X[((size_t)b * C2 + 2 * g + c) * HW + gy * Ww + gx];
        xs[c][yy][xx] = v;
    }
    __syncthreads();

    const int x  = tid & 31;
    const int yb = (tid >> 5) * 4;
    #pragma unroll
    for (int j = 0; j < 4; ++j) {
        int y = yb + j;
        float a0 = 0.f, a1 = 0.f;
        #pragma unroll
        for (int c = 0; c < 2; ++c)
            #pragma unroll
            for (int ky = 0; ky < 3; ++ky)
                #pragma unroll
                for (int kx = 0; kx < 3; ++kx) {
                    float v = xs[c][y + ky][x + kx];
                    a0 += v * ws[c * 9 + ky * 3 + kx];
                    a1 += v * ws[18 + c * 9 + ky * 3 + kx];
                }
        size_t o = ((size_t)b * C2 + 2 * g) * HW + (ty0 + y) * Ww + tx0 + x;
        Y[o]      = a0;
        Y[o + HW] = a1;
    }
}

// cat: channel-pair thread; writes CAT fp32 + CATH packed in one pass.
__global__ void catpack_kernel(const float* __restrict__ QKV,
                               const float* __restrict__ Yin,
                               float* __restrict__ CAT,
                               uint4* __restrict__ CATH)
{
    const int NP = C2 / 2;
    const int N4 = HW / 4;
    int i = blockIdx.x * 256 + threadIdx.x;
    if (i >= Bn * NP * N4) return;
    int p4 = i % N4;
    int pr = (i / N4) % NP;
    int b  = i / (N4 * NP);
    int c0 = 2 * pr;
    float4 a, bv;
    if (c0 < Cc) {
        a  = reinterpret_cast<const float4*>(QKV + ((size_t)b * C2 + c0) * HW)[p4];
        bv = reinterpret_cast<const float4*>(QKV + ((size_t)b * C2 + c0 + 1) * HW)[p4];
    } else {
        a  = reinterpret_cast<const float4*>(Yin + ((size_t)b * Cc + (c0 - Cc)) * HW)[p4];
        bv = reinterpret_cast<const float4*>(Yin + ((size_t)b * Cc + (c0 - Cc) + 1) * HW)[p4];
    }
    reinterpret_cast<float4*>(CAT + ((size_t)b * C2 + c0) * HW)[p4]     = a;
    reinterpret_cast<float4*>(CAT + ((size_t)b * C2 + c0 + 1) * HW)[p4] = bv;
    uint4 o;
    o.x = pack_h2(a.x, bv.x);
    o.y = pack_h2(a.y, bv.y);
    o.z = pack_h2(a.z, bv.z);
    o.w = pack_h2(a.w, bv.w);
    CATH[((size_t)b * NP + pr) * N4 + p4] = o;
}

// 2x2 avg pool, packed-only output
__global__ void poolpack_kernel(const float* __restrict__ X, uint4* __restrict__ Yp)
{
    const int NP   = C2 / 2;
    const int OHW4 = 48 * 48 / 4;
    int i = blockIdx.x * 256 + threadIdx.x;
    if (i >= Bn * NP * OHW4) return;
    int r  = i % OHW4;
    int pr = (i / OHW4) % NP;
    int b  = i / (OHW4 * NP);
    int y  = r / 12;
    int x8 = (r % 12) * 8;
    float pv[2][4];
    #pragma unroll
    for (int c = 0; c < 2; ++c) {
        const float* xp = X + ((size_t)b * C2 + 2 * pr + c) * HW;
        float4 r0a = *reinterpret_cast<const float4*>(xp + (2 * y) * Ww + x8);
        float4 r0b = *reinterpret_cast<const float4*>(xp + (2 * y) * Ww + x8 + 4);
        float4 r1a = *reinterpret_cast<const float4*>(xp + (2 * y + 1) * Ww + x8);
        float4 r1b = *reinterpret_cast<const float4*>(xp + (2 * y + 1) * Ww + x8 + 4);
        pv[c][0] = (r0a.x + r0a.y + r1a.x + r1a.y) * 0.25f;
        pv[c][1] = (r0a.z + r0a.w + r1a.z + r1a.w) * 0.25f;
        pv[c][2] = (r0b.x + r0b.y + r1b.x + r1b.y) * 0.25f;
        pv[c][3] = (r0b.z + r0b.w + r1b.z + r1b.w) * 0.25f;
    }
    uint4 o;
    o.x = pack_h2(pv[0][0], pv[1][0]);
    o.y = pack_h2(pv[0][1], pv[1][1]);
    o.z = pack_h2(pv[0][2], pv[1][2]);
    o.w = pack_h2(pv[0][3], pv[1][3]);
    Yp[((size_t)b * NP + pr) * OHW4 + r] = o;
}

// SCH = pack(SC * sigmoid(CAT + upsample(K2)))
__global__ void sigmulpack_kernel(const float* __restrict__ SC,
                                  const float* __restrict__ CAT,
                                  const float* __restrict__ K2,
                                  uint4* __restrict__ SCH)
{
    const int NP = C2 / 2;
    const int N4 = HW / 4;
    int i = blockIdx.x * 256 + threadIdx.x;
    if (i >= Bn * NP * N4) return;
    int p4 = i % N4;
    int pr = (i / N4) % NP;
    int b  = i / (N4 * NP);
    int p  = p4 * 4;
    int y  = p / Ww, x = p % Ww;
    int iy = (y * 46) / 96;
    int ix0 = ((x + 0) * 46) / 96;
    int ix1 = ((x + 1) * 46) / 96;
    int ix2 = ((x + 2) * 46) / 96;
    int ix3 = ((x + 3) * 46) / 96;
    float sv2[2][4];
    #pragma unroll
    for (int c = 0; c < 2; ++c) {
        size_t bc = (size_t)b * C2 + 2 * pr + c;
        const float* k2r = K2 + bc * (46 * 46) + iy * 46;
        float4 cv = reinterpret_cast<const float4*>(CAT + bc * HW)[p4];
        float4 sv = reinterpret_cast<const float4*>(SC + bc * HW)[p4];
        sv2[c][0] = sv.x / (1.f + expf(-(cv.x + k2r[ix0])));
        sv2[c][1] = sv.y / (1.f + expf(-(cv.y + k2r[ix1])));
        sv2[c][2] = sv.z / (1.f + expf(-(cv.z + k2r[ix2])));
        sv2[c][3] = sv.w / (1.f + expf(-(cv.w + k2r[ix3])));
    }
    uint4 o;
    o.x = pack_h2(sv2[0][0], sv2[1][0]);
    o.y = pack_h2(sv2[0][1], sv2[1][1]);
    o.z = pack_h2(sv2[0][2], sv2[1][2]);
    o.w = pack_h2(sv2[0][3], sv2[1][3]);
    SCH[((size_t)b * NP + pr) * N4 + p4] = o;
}

// ---------------------------------------------------------------------------
// fused deformable conv; float4 weight LDS; writes packed half2 relu output.
// ---------------------------------------------------------------------------
__global__ __launch_bounds__(128)
void deform_kernel(const float* __restrict__ Q,
                   const float* __restrict__ OFF,
                   const float* __restrict__ W,
                   const float* __restrict__ Bias,
                   uint32_t* __restrict__ Yp)
{
    __shared__ __align__(16) float ws2[216 * 24];
    const int g = blockIdx.y;
    const int b = blockIdx.z;
    const int tid = threadIdx.x;

    for (int e = tid; e < 216 * 24; e += 128) {
        int it = e / 24;
        int o  = e - it * 24;
        ws2[e] = W[(size_t)(g * CG + o) * 216 + it];
    }
    __syncthreads();

    int p = blockIdx.x * 128 + tid;
    int y = p / Ww, x = p % Ww;
    const float* offb = OFF + (size_t)b * 18 * HW;

    float acc[24];
    #pragma unroll
    for (int o = 0; o < 24; ++o) acc[o] = Bias[g * CG + o];

    const float* qc = Q + ((size_t)b * C2 + g * CG) * HW;

    for (int t = 0; t < 9; ++t) {
        float dy = offb[(size_t)(2 * t) * HW + p];
        float dx = offb[(size_t)(2 * t + 1) * HW + p];
        float m  = 1.f / (1.f + expf(-offb[(size_t)t * HW + p]));
        float py = dy + (float)(y - 1 + t / 3);
        float px = dx + (float)(x - 1 + t % 3);
        float y0f = floorf(py), x0f = floorf(px);
        int   y0 = (int)y0f,    x0 = (int)x0f;
        float fy = py - y0f,    fx = px - x0f;
        float w00 = (1.f - fy) * (1.f - fx);
        float w01 = (1.f - fy) * fx;
        float w10 = fy * (1.f - fx);
        float w11 = fy * fx;
        bool vy0 = (y0 >= 0 && y0 <= Hh - 1), vy1 = (y0 + 1 >= 0 && y0 + 1 <= Hh - 1);
        bool vx0 = (x0 >= 0 && x0 <= Ww - 1), vx1 = (x0 + 1 >= 0 && x0 + 1 <= Ww - 1);
        int cy0 = min(max(y0, 0), Hh - 1),     cy1 = min(max(y0 + 1, 0), Hh - 1);
        int cx0 = min(max(x0, 0), Ww - 1),     cx1 = min(max(x0 + 1, 0), Ww - 1);
        int i00 = cy0 * Ww + cx0, i01 = cy0 * Ww + cx1;
        int i10 = cy1 * Ww + cx0, i11 = cy1 * Ww + cx1;
        w00 = (vy0 && vx0) ? w00 * m : 0.f;
        w01 = (vy0 && vx1) ? w01 * m : 0.f;
        w10 = (vy1 && vx0) ? w10 * m : 0.f;
        w11 = (vy1 && vx1) ? w11 * m : 0.f;

        #pragma unroll
        for (int i = 0; i < 24; ++i) {
            const float* qp = qc + (size_t)i * HW;
            float val = w00 * qp[i00] + w01 * qp[i01] + w10 * qp[i10] + w11 * qp[i11];
            const float4* wr4 = reinterpret_cast<const float4*>(&ws2[(i * 9 + t) * 24]);
            #pragma unroll
            for (int o4 = 0; o4 < 6; ++o4) {
                float4 w4 = wr4[o4];
                acc[4 * o4 + 0] += val * w4.x;
                acc[4 * o4 + 1] += val * w4.y;
                acc[4 * o4 + 2] += val * w4.z;
                acc[4 * o4 + 3] += val * w4.w;
            }
        }
    }
    #pragma unroll
    for (int u = 0; u < 12; ++u) {
        uint32_t v = pack_h2(fmaxf(acc[2 * u], 0.f), fmaxf(acc[2 * u + 1], 0.f));
        Yp[((size_t)b * (Cc / 2) + g * 12 + u) * HW + p] = v;
    }
}

// ---------------------------------------------------------------------------
// row L2 norms (float4)
// ---------------------------------------------------------------------------
__global__ void rownorm_kernel(const float* __restrict__ QKV,
                               const float* __restrict__ Kb,
                               float* __restrict__ QN,
                               float* __restrict__ KN)
{
    int row   = blockIdx.x;
    int which = row / (Bn * Cc);
    row %= (Bn * Cc);
    int b = row / Cc, c = row % Cc;
    const float* src = which ? (Kb + ((size_t)b * Cc + c) * HW)
                             : (QKV + ((size_t)b * C2 + c) * HW);
    float s = 0.f;
    for (int n = threadIdx.x; n < HW / 4; n += 256) {
        float4 v = reinterpret_cast<const float4*>(src)[n];
        s += v.x * v.x + v.y * v.y + v.z * v.z + v.w * v.w;
    }
    __shared__ float sm[256];
    sm[threadIdx.x] = s;
    __syncthreads();
    for (int d = 128; d > 0; d >>= 1) {
        if (threadIdx.x < d) sm[threadIdx.x] += sm[threadIdx.x + d];
        __syncthreads();
    }
    if (threadIdx.x == 0) {
        float nrm = fmaxf(sqrtf(sm[0]), 1e-12f);
        (which ? KN : QN)[b * Cc + c] = nrm;
    }
}

// ---------------------------------------------------------------------------
// attention: one block per (b,h).  K-head staged through smem.
// ---------------------------------------------------------------------------
#define CNK 384
__global__ __launch_bounds__(256)
void attn2_kernel(const float* __restrict__ QKV,
                  const float* __restrict__ Kb,
                  const float* __restrict__ QN,
                  const float* __restrict__ KN,
                  const float* __restrict__ TEMP,
                  float* __restrict__ ATTN)
{
    __shared__ float ks_[24][CNK + 8];
    __shared__ float logits[24][24];

    const int b = blockIdx.x >> 3;
    const int h = blockIdx.x & 7;
    const int tid  = threadIdx.x;
    const int wid  = tid >> 5;
    const int lane = tid & 31;

    const float* qh = QKV + ((size_t)b * C2 + h * HD) * HW;
    const float* kh = Kb  + ((size_t)b * Cc + h * HD) * HW;

    float acc[3][24];
    #pragma unroll
    for (int r = 0; r < 3; ++r)
        #pragma unroll
        for (int j = 0; j < 24; ++j) acc[r][j] = 0.f;

    const float* q0p = qh + (size_t)(3 * wid + 0) * HW;
    const float* q1p = qh + (size_t)(3 * wid + 1) * HW;
    const float* q2p = qh + (size_t)(3 * wid + 2) * HW;

    for (int n0 = 0; n0 < HW; n0 += CNK) {
        __syncthreads();
        for (int e = tid; e < 24 * (CNK / 4); e += 256) {
            int j = e / (CNK / 4);
            int c = e - j * (CNK / 4);
            float4 v = *reinterpret_cast<const float4*>(kh + (size_t)j * HW + n0 + c * 4);
            ks_[j][c * 4 + 0] = v.x;
            ks_[j][c * 4 + 1] = v.y;
            ks_[j][c * 4 + 2] = v.z;
            ks_[j][c * 4 + 3] = v.w;
        }
        __syncthreads();

        for (int i = lane; i < CNK; i += 32) {
            int n = n0 + i;
            float q0 = q0p[n], q1 = q1p[n], q2 = q2p[n];
            #pragma unroll
            for (int j = 0; j < 24; ++j) {
                float kv = ks_[j][i];
                acc[0][j] += q0 * kv;
                acc[1][j] += q1 * kv;
                acc[2][j] += q2 * kv;
            }
        }
    }

    #pragma unroll
    for (int r = 0; r < 3; ++r)
        #pragma unroll
        for (int j = 0; j < 24; ++j) {
            float v = acc[r][j];
            for (int o = 16; o > 0; o >>= 1) v += __shfl_down_sync(0xffffffffu, v, o);
            if (lane == 0) logits[wid * 3 + r][j] = v;
        }
    __syncthreads();

    if (tid < 24) {
        int i = tid;
        float qn = QN[b * Cc + h * HD + i];
        float tp = TEMP[h];
        float s[24];
        float mx = -1e30f;
        #pragma unroll
        for (int j = 0; j < 24; ++j) {
            s[j] = logits[i][j] / (qn * KN[b * Cc + h * HD + j]) * tp;
            mx = fmaxf(mx, s[j]);
        }
        float sum = 0.f;
        #pragma unroll
        for (int j = 0; j < 24; ++j) { s[j] = expf(s[j] - mx); sum += s[j]; }
        float inv = 1.f / sum;
        #pragma unroll
        for (int j = 0; j < 24; ++j)
            ATTN[(((size_t)b * NH + h) * HD + i) * HD + j] = s[j] * inv;
    }
}

// out = attn @ v ; writes packed half2 directly
__global__ void attnv_kernel(const float* __restrict__ ATTN,
                             const float* __restrict__ QKV,
                             uint32_t* __restrict__ AOp)
{
    int h = blockIdx.y, b = blockIdx.z;
    int n = blockIdx.x * 256 + threadIdx.x;
    __shared__ float a_s[HD * HD];
    for (int e = threadIdx.x; e < HD * HD; e += 256)
        a_s[e] = ATTN[((size_t)b * NH + h) * HD * HD + e];
    __syncthreads();
    const float* vb = QKV + ((size_t)b * C2 + Cc + h * HD) * HW;
    float acc[HD] = {};
    #pragma unroll
    for (int j = 0; j < HD; ++j) {
        float vv = vb[(size_t)j * HW + n];
        #pragma unroll
        for (int i = 0; i < HD; ++i) acc[i] += a_s[i * HD + j] * vv;
    }
    #pragma unroll
    for (int u = 0; u < HD / 2; ++u)
        AOp[((size_t)b * (Cc / 2) + h * (HD / 2) + u) * HW + n] =
            pack_h2(acc[2 * u], acc[2 * u + 1]);
}

// ---------------------------------------------------------------------------
// launcher
// ---------------------------------------------------------------------------
extern "C" void kernel_launch(void* const* d_in, const int* in_sizes, int n_in,
                              void* d_out, int out_size)
{
    const float* x           = (const float*)d_in[0];
    const float* y           = (const float*)d_in[1];
    const float* temperature = (const float*)d_in[2];
    const float* qkv_w       = (const float*)d_in[3];
    const float* qkv_conv_w  = (const float*)d_in[4];
    const float* proj_w      = (const float*)d_in[5];
    const float* k2_w        = (const float*)d_in[6];
    const float* k3_w        = (const float*)d_in[7];
    const float* k4_w        = (const float*)d_in[8];
    const float* deform_w    = (const float*)d_in[9];
    const float* deform_b    = (const float*)d_in[10];
    const float* pw_w        = (const float*)d_in[11];
    const float* pw_b        = (const float*)d_in[12];
    float* out = (float*)d_out;

    float* S = nullptr;
    cudaGetSymbolAddress((void**)&S, g_scratch);
    float* QKV1 = S + OFF_QKV1;
    float* QKV  = S + OFF_QKV;
    float* CAT  = S + OFF_CAT;
    float* SC   = S + OFF_SC;
    float* K2   = S + OFF_K2;
    float* OFFb = S + OFF_OFF;
    float* Kb   = S + OFF_K;
    float* QN   = S + OFF_QN;
    float* KN   = S + OFF_KN;
    float* ATTN = S + OFF_ATTN;
    uint32_t* WK3H   = (uint32_t*)(S + OFF_WK3H);
    uint32_t* WK2H   = (uint32_t*)(S + OFF_WK2H);
    uint32_t* WK4H   = (uint32_t*)(S + OFF_WK4H);
    uint32_t* WQKVH  = (uint32_t*)(S + OFF_WQKVH);
    uint32_t* WPWH   = (uint32_t*)(S + OFF_WPWH);
    uint32_t* WPROJH = (uint32_t*)(S + OFF_WPROJH);
    uint32_t* XH    = (uint32_t*)(S + OFF_XH);
    uint32_t* CATH  = (uint32_t*)(S + OFF_CATH);
    uint32_t* POOLH = (uint32_t*)(S + OFF_POOLH);
    uint32_t* SCH   = (uint32_t*)(S + OFF_SCH);
    uint32_t* FEATH = (uint32_t*)(S + OFF_FEATH);
    uint32_t* AOH   = (uint32_t*)(S + OFF_AOH);

    // 0) merged prep: all weight packs + x halfpack (single launch)
    prep_kernel<<<(2316672 + 255) / 256, 256>>>(
        k3_w, k2_w, k4_w, qkv_w, pw_w, proj_w, x,
        WK3H, WK2H, WK4H, WQKVH, WPWH, WPROJH, (uint4*)XH);

    // 1) qkv 1x1
    conv_mma<1, 4><<<dim3(HW / 128, C2 / 128, Bn), 256>>>(
        WQKVH, XH, QKV1, nullptr, C2, Cc, Hh, Ww, Hh, Ww, 0);
    // 2) grouped 3x3 (groups=192)
    dwconv2_kernel<<<dim3(9, 192, Bn), 256>>>(QKV1, qkv_conv_w, QKV);
    // 3) cat (fp32 + packed in one pass)
    catpack_kernel<<<(Bn * 192 * 2304 + 255) / 256, 256>>>(QKV, y, CAT, (uint4*)CATH);
    // 4) avg pool 2x2 (packed only)
    poolpack_kernel<<<(Bn * 192 * 576 + 255) / 256, 256>>>(CAT, (uint4*)POOLH);
    // 5) k3 conv 3x3 pad=1  (launch index 5 -> ncu profile slot)
    conv_mma<3, 4><<<dim3(HW / 128, C2 / 128, Bn), 256>>>(
        WK3H, CATH, SC, nullptr, C2, C2, Hh, Ww, Hh, Ww, 1);
    // 6) k2 conv 3x3 pad=0 : 48x48 -> 46x46
    conv_mma<3, 4><<<dim3((46 * 46 + 127) / 128, C2 / 128, Bn), 256>>>(
        WK2H, POOLH, K2, nullptr, C2, C2, 48, 48, 46, 46, 0);
    // 7) SCH = pack(SC * sigmoid(CAT + upsample(K2)))
    sigmulpack_kernel<<<(Bn * 192 * 2304 + 255) / 256, 256>>>(SC, CAT, K2, (uint4*)SCH);
    // 8) offset = conv3x3(sc, k4, pad=1), M=18
    conv_mma<3, 1><<<dim3(HW / 128, 1, Bn), 256>>>(
        WK4H, SCH, OFFb, nullptr, 18, C2, Hh, Ww, Hh, Ww, 1);
    // 9) deformable conv -> packed relu output
    deform_kernel<<<dim3(HW / 128, Gg, Bn), 128>>>(QKV, OFFb, deform_w, deform_b, FEATH);
    // 10) k = 1x1(FEAT) + pw_b
    conv_mma<1, 4><<<dim3(HW / 128, (Cc + 127) / 128, Bn), 256>>>(
        WPWH, FEATH, Kb, pw_b, Cc, Cc, Hh, Ww, Hh, Ww, 0);
    // 11) row norms
    rownorm_kernel<<<2 * Bn * Cc, 256>>>(QKV, Kb, QN, KN);
    // 12) attention logits + softmax
    attn2_kernel<<<Bn * NH, 256>>>(QKV, Kb, QN, KN, temperature, ATTN);
    // 13) out = attn @ v (packed output)
    attnv_kernel<<<dim3(HW / 256, NH, Bn), 256>>>(ATTN, QKV, AOH);
    // 14) final 1x1 proj -> d_out
    conv_mma<1, 4><<<dim3(HW / 128, (Cc + 127) / 128, Bn), 256>>>(
        WPROJH, AOH, out, nullptr, Cc, Cc, Hh, Ww, Hh, Ww, 0);
}